// round 4
// baseline (speedup 1.0000x reference)
#include <cuda_runtime.h>
#include <math.h>
#include <stdint.h>

// Problem dims
#define BB 2
#define SS 2048
#define EE 1024
#define HH 16
#define DD 64
#define MM (BB * SS)      // 4096 rows
#define NQKV (3 * EE)     // 3072

// ---------------- scratch (static device globals; no allocation) ----------------
__device__ float g_q[BB * HH * SS * DD];   // [B,H,S,D]
__device__ float g_k[BB * HH * SS * DD];
__device__ float g_v[BB * HH * SS * DD];
__device__ float g_ctx[MM * EE];           // [B,S,E]

// ---------------- tf32 helpers (R2-proven) ----------------
__device__ __forceinline__ uint32_t f2tf32(float x) {
    uint32_t r;
    asm("cvt.rna.tf32.f32 %0, %1;" : "=r"(r) : "f"(x));
    return r;
}

__device__ __forceinline__ void mma_tf32(float* c, const uint32_t* a, const uint32_t* b) {
    asm volatile(
        "mma.sync.aligned.m16n8k8.row.col.f32.tf32.tf32.f32 "
        "{%0,%1,%2,%3}, {%4,%5,%6,%7}, {%8,%9}, {%0,%1,%2,%3};"
        : "+f"(c[0]), "+f"(c[1]), "+f"(c[2]), "+f"(c[3])
        : "r"(a[0]), "r"(a[1]), "r"(a[2]), "r"(a[3]),
          "r"(b[0]), "r"(b[1]));
}

#define PITCH 136

// =================================================================================
// Kernel 1: QKV GEMM (verbatim from R2 — known good)
// =================================================================================
__global__ __launch_bounds__(256, 2) void qkv_gemm_tf32(
    const float* __restrict__ X, const float* __restrict__ W,
    const float* __restrict__ bias)
{
    __shared__ float Ah[16][PITCH], Al[16][PITCH];
    __shared__ float Bh[16][PITCH], Bl[16][PITCH];

    const int bn = blockIdx.x, bm = blockIdx.y;
    const int tid = threadIdx.x;
    const int warp = tid >> 5, lane = tid & 31;
    const int g = lane >> 2, tg = lane & 3;
    const int wm = (warp >> 2) * 64;
    const int wn = (warp & 3) * 32;
    const int row0 = bm * 128, col0 = bn * 128;

    float C[4][4][4];
#pragma unroll
    for (int mi = 0; mi < 4; mi++)
#pragma unroll
        for (int ni = 0; ni < 4; ni++)
#pragma unroll
            for (int t = 0; t < 4; t++) C[mi][ni][t] = 0.f;

    for (int k0 = 0; k0 < EE; k0 += 16) {
#pragma unroll
        for (int it = 0; it < 2; it++) {
            int f4 = tid + it * 256;
            int r = f4 >> 2;
            int c = (f4 & 3) << 2;
            float4 v = *(const float4*)(X + (size_t)(row0 + r) * EE + k0 + c);
            float xs[4] = {v.x, v.y, v.z, v.w};
#pragma unroll
            for (int j = 0; j < 4; j++) {
                float hf = __uint_as_float(f2tf32(xs[j]));
                Ah[c + j][r] = hf;
                Al[c + j][r] = xs[j] - hf;
            }
        }
#pragma unroll
        for (int it = 0; it < 2; it++) {
            int f4 = tid + it * 256;
            int kk = f4 >> 5;
            int c = (f4 & 31) << 2;
            float4 v = *(const float4*)(W + (size_t)(k0 + kk) * NQKV + col0 + c);
            float xs[4] = {v.x, v.y, v.z, v.w};
            float hf[4], lf[4];
#pragma unroll
            for (int j = 0; j < 4; j++) {
                hf[j] = __uint_as_float(f2tf32(xs[j]));
                lf[j] = xs[j] - hf[j];
            }
            *(float4*)&Bh[kk][c] = make_float4(hf[0], hf[1], hf[2], hf[3]);
            *(float4*)&Bl[kk][c] = make_float4(lf[0], lf[1], lf[2], lf[3]);
        }
        __syncthreads();

#pragma unroll
        for (int ks = 0; ks < 2; ks++) {
            const int kb = ks * 8;
            uint32_t ah[4][4], al[4][4], bh[4][2], bl[4][2];
#pragma unroll
            for (int mi = 0; mi < 4; mi++) {
                int m = wm + mi * 16 + g;
                ah[mi][0] = __float_as_uint(Ah[kb + tg][m]);
                ah[mi][1] = __float_as_uint(Ah[kb + tg][m + 8]);
                ah[mi][2] = __float_as_uint(Ah[kb + tg + 4][m]);
                ah[mi][3] = __float_as_uint(Ah[kb + tg + 4][m + 8]);
                al[mi][0] = __float_as_uint(Al[kb + tg][m]);
                al[mi][1] = __float_as_uint(Al[kb + tg][m + 8]);
                al[mi][2] = __float_as_uint(Al[kb + tg + 4][m]);
                al[mi][3] = __float_as_uint(Al[kb + tg + 4][m + 8]);
            }
#pragma unroll
            for (int ni = 0; ni < 4; ni++) {
                int n = wn + ni * 8 + g;
                bh[ni][0] = __float_as_uint(Bh[kb + tg][n]);
                bh[ni][1] = __float_as_uint(Bh[kb + tg + 4][n]);
                bl[ni][0] = __float_as_uint(Bl[kb + tg][n]);
                bl[ni][1] = __float_as_uint(Bl[kb + tg + 4][n]);
            }
#pragma unroll
            for (int mi = 0; mi < 4; mi++)
#pragma unroll
                for (int ni = 0; ni < 4; ni++) {
                    mma_tf32(C[mi][ni], ah[mi], bh[ni]);
                    mma_tf32(C[mi][ni], ah[mi], bl[ni]);
                    mma_tf32(C[mi][ni], al[mi], bh[ni]);
                }
        }
        __syncthreads();
    }

#pragma unroll
    for (int mi = 0; mi < 4; mi++) {
#pragma unroll
        for (int half = 0; half < 2; half++) {
            int r = row0 + wm + mi * 16 + g + half * 8;
            int b_ = r >> 11;
            int s  = r & 2047;
#pragma unroll
            for (int ni = 0; ni < 4; ni++) {
#pragma unroll
                for (int c01 = 0; c01 < 2; c01++) {
                    int n = col0 + wn + ni * 8 + 2 * tg + c01;
                    float v = C[mi][ni][half * 2 + c01] + bias[n];
                    int which = n >> 10;
                    int e = n & 1023;
                    int h = e >> 6, d = e & 63;
                    float* dst = (which == 0) ? g_q : (which == 1) ? g_k : g_v;
                    dst[(size_t)(((b_ * HH) + h) * SS + s) * DD + d] = v;
                }
            }
        }
    }
}

// =================================================================================
// Kernel 3: proj GEMM (verbatim from R2 — known good)
// =================================================================================
__global__ __launch_bounds__(256, 2) void proj_gemm_tf32(
    const float* __restrict__ W, const float* __restrict__ bias,
    float* __restrict__ out)
{
    __shared__ float Ah[16][PITCH], Al[16][PITCH];
    __shared__ float Bh[16][PITCH], Bl[16][PITCH];

    const int bn = blockIdx.x, bm = blockIdx.y;
    const int tid = threadIdx.x;
    const int warp = tid >> 5, lane = tid & 31;
    const int g = lane >> 2, tg = lane & 3;
    const int wm = (warp >> 2) * 64;
    const int wn = (warp & 3) * 32;
    const int row0 = bm * 128, col0 = bn * 128;

    float C[4][4][4];
#pragma unroll
    for (int mi = 0; mi < 4; mi++)
#pragma unroll
        for (int ni = 0; ni < 4; ni++)
#pragma unroll
            for (int t = 0; t < 4; t++) C[mi][ni][t] = 0.f;

    for (int k0 = 0; k0 < EE; k0 += 16) {
#pragma unroll
        for (int it = 0; it < 2; it++) {
            int f4 = tid + it * 256;
            int r = f4 >> 2;
            int c = (f4 & 3) << 2;
            float4 v = *(const float4*)(g_ctx + (size_t)(row0 + r) * EE + k0 + c);
            float xs[4] = {v.x, v.y, v.z, v.w};
#pragma unroll
            for (int j = 0; j < 4; j++) {
                float hf = __uint_as_float(f2tf32(xs[j]));
                Ah[c + j][r] = hf;
                Al[c + j][r] = xs[j] - hf;
            }
        }
#pragma unroll
        for (int it = 0; it < 2; it++) {
            int f4 = tid + it * 256;
            int kk = f4 >> 5;
            int c = (f4 & 31) << 2;
            float4 v = *(const float4*)(W + (size_t)(k0 + kk) * EE + col0 + c);
            float xs[4] = {v.x, v.y, v.z, v.w};
            float hf[4], lf[4];
#pragma unroll
            for (int j = 0; j < 4; j++) {
                hf[j] = __uint_as_float(f2tf32(xs[j]));
                lf[j] = xs[j] - hf[j];
            }
            *(float4*)&Bh[kk][c] = make_float4(hf[0], hf[1], hf[2], hf[3]);
            *(float4*)&Bl[kk][c] = make_float4(lf[0], lf[1], lf[2], lf[3]);
        }
        __syncthreads();

#pragma unroll
        for (int ks = 0; ks < 2; ks++) {
            const int kb = ks * 8;
            uint32_t ah[4][4], al[4][4], bh[4][2], bl[4][2];
#pragma unroll
            for (int mi = 0; mi < 4; mi++) {
                int m = wm + mi * 16 + g;
                ah[mi][0] = __float_as_uint(Ah[kb + tg][m]);
                ah[mi][1] = __float_as_uint(Ah[kb + tg][m + 8]);
                ah[mi][2] = __float_as_uint(Ah[kb + tg + 4][m]);
                ah[mi][3] = __float_as_uint(Ah[kb + tg + 4][m + 8]);
                al[mi][0] = __float_as_uint(Al[kb + tg][m]);
                al[mi][1] = __float_as_uint(Al[kb + tg][m + 8]);
                al[mi][2] = __float_as_uint(Al[kb + tg + 4][m]);
                al[mi][3] = __float_as_uint(Al[kb + tg + 4][m + 8]);
            }
#pragma unroll
            for (int ni = 0; ni < 4; ni++) {
                int n = wn + ni * 8 + g;
                bh[ni][0] = __float_as_uint(Bh[kb + tg][n]);
                bh[ni][1] = __float_as_uint(Bh[kb + tg + 4][n]);
                bl[ni][0] = __float_as_uint(Bl[kb + tg][n]);
                bl[ni][1] = __float_as_uint(Bl[kb + tg + 4][n]);
            }
#pragma unroll
            for (int mi = 0; mi < 4; mi++)
#pragma unroll
                for (int ni = 0; ni < 4; ni++) {
                    mma_tf32(C[mi][ni], ah[mi], bh[ni]);
                    mma_tf32(C[mi][ni], ah[mi], bl[ni]);
                    mma_tf32(C[mi][ni], al[mi], bh[ni]);
                }
        }
        __syncthreads();
    }

#pragma unroll
    for (int mi = 0; mi < 4; mi++) {
#pragma unroll
        for (int half = 0; half < 2; half++) {
            int r = row0 + wm + mi * 16 + g + half * 8;
#pragma unroll
            for (int ni = 0; ni < 4; ni++) {
#pragma unroll
                for (int c01 = 0; c01 < 2; c01++) {
                    int n = col0 + wn + ni * 8 + 2 * tg + c01;
                    out[(size_t)r * EE + n] = C[mi][ni][half * 2 + c01] + bias[n];
                }
            }
        }
    }
}

// =================================================================================
// Kernel 2: single-pass causal attention with tf32 MMA (R2-proven fragment style).
// Block = (qb 128 q-rows, h, b); 8 warps x 16 q-rows; keys in chunks of 64.
// Writes unnormalized e=exp(s) to attn_w, P staged in SMEM for the PV MMA,
// then in-place rescale + upper-triangle zero-fill.
// =================================================================================
// SMEM float offsets
#define OQH 0
#define OQL (OQH + 64 * 132)      //  8448  Q hi [d][row]
#define OKH (OQL + 64 * 132)      // 16896  K hi [d][key64]
#define OKL (OKH + 64 * 68)       // 21248
#define OVH (OKL + 64 * 68)       // 25600  V hi [key64][d]
#define OVL (OVH + 64 * 68)       // 29952
#define OPS (OVL + 64 * 68)       // 34304  P [row128][key64]
#define OLS (OPS + 128 * 68)      // 43008  row sums
#define ATT_FLOATS (OLS + 128)
#define ATT_SMEM (ATT_FLOATS * 4) // 172544 bytes

__global__ __launch_bounds__(256) void attn_kernel(float* __restrict__ attn_w)
{
    extern __shared__ float sm[];
    float* Qh = sm + OQH;
    float* Ql = sm + OQL;
    float* Kh = sm + OKH;
    float* Kl = sm + OKL;
    float* Vh = sm + OVH;
    float* Vl = sm + OVL;
    float* Ps = sm + OPS;
    float* Ls = sm + OLS;

    const int qb = (int)gridDim.x - 1 - (int)blockIdx.x;   // heavy blocks first
    const int h = blockIdx.y, b = blockIdx.z;
    const int tid = threadIdx.x;
    const int warp = tid >> 5, lane = tid & 31;
    const int g = lane >> 2, tg = lane & 3;

    const float* Qg = g_q + ((size_t)(b * HH + h) * SS + qb * 128) * DD;
    const float* Kg = g_k + (size_t)(b * HH + h) * SS * DD;
    const float* Vg = g_v + (size_t)(b * HH + h) * SS * DD;

    // ---- stage Q (pre-scaled by 1/8), transposed split into Qh/Ql[d][row] ----
#pragma unroll
    for (int it = 0; it < 8; it++) {
        int f4 = tid + it * 256;          // 0..2047
        int r = f4 >> 4, c = (f4 & 15) << 2;
        float4 v = *(const float4*)(Qg + r * 64 + c);
        float xs[4] = {v.x * 0.125f, v.y * 0.125f, v.z * 0.125f, v.w * 0.125f};
#pragma unroll
        for (int j = 0; j < 4; j++) {
            float hf = __uint_as_float(f2tf32(xs[j]));
            Qh[(c + j) * 132 + r] = hf;
            Ql[(c + j) * 132 + r] = xs[j] - hf;
        }
    }
    __syncthreads();

    // ---- Q A-frags, register resident (8 k-steps of 8) ----
    uint32_t qa_h[8][4], qa_l[8][4];
    {
        int m = warp * 16 + g;
#pragma unroll
        for (int ks = 0; ks < 8; ks++) {
            qa_h[ks][0] = __float_as_uint(Qh[(ks * 8 + tg) * 132 + m]);
            qa_h[ks][1] = __float_as_uint(Qh[(ks * 8 + tg) * 132 + m + 8]);
            qa_h[ks][2] = __float_as_uint(Qh[(ks * 8 + tg + 4) * 132 + m]);
            qa_h[ks][3] = __float_as_uint(Qh[(ks * 8 + tg + 4) * 132 + m + 8]);
            qa_l[ks][0] = __float_as_uint(Ql[(ks * 8 + tg) * 132 + m]);
            qa_l[ks][1] = __float_as_uint(Ql[(ks * 8 + tg) * 132 + m + 8]);
            qa_l[ks][2] = __float_as_uint(Ql[(ks * 8 + tg + 4) * 132 + m]);
            qa_l[ks][3] = __float_as_uint(Ql[(ks * 8 + tg + 4) * 132 + m + 8]);
        }
    }

    float accO[8][4];
#pragma unroll
    for (int dt = 0; dt < 8; dt++)
#pragma unroll
        for (int t = 0; t < 4; t++) accO[dt][t] = 0.f;
    float l0 = 0.f, l1 = 0.f;

    const int rowL = warp * 16 + g;             // block-local row of c0/c1
    const int row0g = qb * 128 + rowL;          // global row
    const size_t wbase = (size_t)(b * HH + h) * SS * SS;
    const int nch = 2 * (qb + 1);

    for (int ch = 0; ch < nch; ch++) {
        __syncthreads();   // protect K/V/Ps of previous chunk
        // ---- stage K chunk [d][key] and V chunk [key][d], split hi/lo ----
#pragma unroll
        for (int it = 0; it < 4; it++) {
            int f4 = tid + it * 256;          // 0..1023
            int key = f4 >> 4, c = (f4 & 15) << 2;
            float4 kv = *(const float4*)(Kg + (size_t)(ch * 64 + key) * 64 + c);
            float xs[4] = {kv.x, kv.y, kv.z, kv.w};
#pragma unroll
            for (int j = 0; j < 4; j++) {
                float hf = __uint_as_float(f2tf32(xs[j]));
                Kh[(c + j) * 68 + key] = hf;
                Kl[(c + j) * 68 + key] = xs[j] - hf;
            }
            float4 vv = *(const float4*)(Vg + (size_t)(ch * 64 + key) * 64 + c);
            float vs[4] = {vv.x, vv.y, vv.z, vv.w};
            float vh[4], vl[4];
#pragma unroll
            for (int j = 0; j < 4; j++) {
                vh[j] = __uint_as_float(f2tf32(vs[j]));
                vl[j] = vs[j] - vh[j];
            }
            *(float4*)&Vh[key * 68 + c] = make_float4(vh[0], vh[1], vh[2], vh[3]);
            *(float4*)&Vl[key * 68 + c] = make_float4(vl[0], vl[1], vl[2], vl[3]);
        }
        __syncthreads();

        const bool masked = (ch >= 2 * qb);
        // ---- scores: 8 n-tiles of 8 keys; exp; store to attn_w + Ps ----
#pragma unroll 1
        for (int nt = 0; nt < 8; nt++) {
            float acc[4] = {0.f, 0.f, 0.f, 0.f};
#pragma unroll
            for (int ks = 0; ks < 8; ks++) {
                int n = nt * 8 + g;
                uint32_t bh[2], bl[2];
                bh[0] = __float_as_uint(Kh[(ks * 8 + tg) * 68 + n]);
                bh[1] = __float_as_uint(Kh[(ks * 8 + tg + 4) * 68 + n]);
                bl[0] = __float_as_uint(Kl[(ks * 8 + tg) * 68 + n]);
                bl[1] = __float_as_uint(Kl[(ks * 8 + tg + 4) * 68 + n]);
                mma_tf32(acc, qa_h[ks], bh);
                mma_tf32(acc, qa_h[ks], bl);
                mma_tf32(acc, qa_l[ks], bh);
            }
            int colb = ch * 64 + nt * 8 + 2 * tg;
            float e0, e1, e2, e3;
            if (masked) {
                e0 = (colb     <= row0g)     ? __expf(acc[0]) : 0.f;
                e1 = (colb + 1 <= row0g)     ? __expf(acc[1]) : 0.f;
                e2 = (colb     <= row0g + 8) ? __expf(acc[2]) : 0.f;
                e3 = (colb + 1 <= row0g + 8) ? __expf(acc[3]) : 0.f;
            } else {
                e0 = __expf(acc[0]); e1 = __expf(acc[1]);
                e2 = __expf(acc[2]); e3 = __expf(acc[3]);
            }
            l0 += e0 + e1; l1 += e2 + e3;
            size_t base = wbase + (size_t)row0g * SS + colb;
            *(float2*)(attn_w + base) = make_float2(e0, e1);
            *(float2*)(attn_w + base + (size_t)8 * SS) = make_float2(e2, e3);
            int pc = nt * 8 + 2 * tg;
            *(float2*)&Ps[rowL * 68 + pc]       = make_float2(e0, e1);
            *(float2*)&Ps[(rowL + 8) * 68 + pc] = make_float2(e2, e3);
        }
        __syncwarp();   // Ps rows are per-warp private; warp-level sync suffices

        // ---- O += P @ V (p as tf32 rna, V hi/lo 2-term) ----
#pragma unroll 1
        for (int ks = 0; ks < 8; ks++) {
            uint32_t pa[4];
            pa[0] = f2tf32(Ps[rowL * 68 + ks * 8 + tg]);
            pa[1] = f2tf32(Ps[(rowL + 8) * 68 + ks * 8 + tg]);
            pa[2] = f2tf32(Ps[rowL * 68 + ks * 8 + tg + 4]);
            pa[3] = f2tf32(Ps[(rowL + 8) * 68 + ks * 8 + tg + 4]);
#pragma unroll
            for (int dt = 0; dt < 8; dt++) {
                uint32_t bh[2], bl[2];
                bh[0] = __float_as_uint(Vh[(ks * 8 + tg) * 68 + dt * 8 + g]);
                bh[1] = __float_as_uint(Vh[(ks * 8 + tg + 4) * 68 + dt * 8 + g]);
                bl[0] = __float_as_uint(Vl[(ks * 8 + tg) * 68 + dt * 8 + g]);
                bl[1] = __float_as_uint(Vl[(ks * 8 + tg + 4) * 68 + dt * 8 + g]);
                mma_tf32(accO[dt], pa, bh);
                mma_tf32(accO[dt], pa, bl);
            }
        }
    }

    // ---- row sums across quad; publish; write normalized O to g_ctx ----
#pragma unroll
    for (int o = 1; o < 4; o <<= 1) {
        l0 += __shfl_xor_sync(0xffffffffu, l0, o);
        l1 += __shfl_xor_sync(0xffffffffu, l1, o);
    }
    if (tg == 0) {
        Ls[rowL] = l0;
        Ls[rowL + 8] = l1;
    }
    float inv0 = 1.f / l0, inv1 = 1.f / l1;

#pragma unroll
    for (int dt = 0; dt < 8; dt++) {
        int col = h * 64 + dt * 8 + 2 * tg;
        *(float2*)&g_ctx[(size_t)(b * SS + row0g) * EE + col] =
            make_float2(accO[dt][0] * inv0, accO[dt][1] * inv0);
        *(float2*)&g_ctx[(size_t)(b * SS + row0g + 8) * EE + col] =
            make_float2(accO[dt][2] * inv1, accO[dt][3] * inv1);
    }
    __syncthreads();

    // ---- rescale written region in place + zero-fill upper triangle ----
    const int lim = (qb + 1) * 128;
    for (int idx = tid; idx < 128 * 512; idx += 256) {
        int row = idx >> 9;
        int c = (idx & 511) << 2;
        size_t p = wbase + (size_t)(qb * 128 + row) * SS + c;
        if (c < lim) {
            float inv = 1.f / Ls[row];
            float4 t = *(float4*)(attn_w + p);
            t.x *= inv; t.y *= inv; t.z *= inv; t.w *= inv;
            *(float4*)(attn_w + p) = t;
        } else {
            *(float4*)(attn_w + p) = make_float4(0.f, 0.f, 0.f, 0.f);
        }
    }
}

// =================================================================================
// launch
// =================================================================================
extern "C" void kernel_launch(void* const* d_in, const int* in_sizes, int n_in,
                              void* d_out, int out_size)
{
    const float* hs = (const float*)d_in[0];
    const float* aw = (const float*)d_in[1];
    const float* ab = (const float*)d_in[2];
    const float* pw = (const float*)d_in[3];
    const float* pb = (const float*)d_in[4];

    float* out      = (float*)d_out;
    float* attn_out = out;                       // [2,2048,1024]
    float* attn_w   = out + (size_t)MM * EE;     // [2,16,2048,2048]

    cudaFuncSetAttribute(attn_kernel, cudaFuncAttributeMaxDynamicSharedMemorySize,
                         ATT_SMEM);

    qkv_gemm_tf32<<<dim3(NQKV / 128, MM / 128), 256>>>(hs, aw, ab);
    attn_kernel<<<dim3(SS / 128, HH, BB), 256, ATT_SMEM>>>(attn_w);
    proj_gemm_tf32<<<dim3(EE / 128, MM / 128), 256>>>(pw, pb, attn_out);
}

// round 5
// speedup vs baseline: 1.0154x; 1.0154x over previous
#include <cuda_runtime.h>
#include <math.h>
#include <stdint.h>

// Problem dims
#define BB 2
#define SS 2048
#define EE 1024
#define HH 16
#define DD 64
#define MM (BB * SS)      // 4096 rows
#define NQKV (3 * EE)     // 3072

// ---------------- scratch (static device globals; no allocation) ----------------
__device__ float g_q[BB * HH * SS * DD];   // [B,H,S,D]
__device__ float g_k[BB * HH * SS * DD];
__device__ float g_v[BB * HH * SS * DD];
__device__ float g_ctx[MM * EE];           // [B,S,E]

// ---------------- tf32 helpers (R2-proven) ----------------
__device__ __forceinline__ uint32_t f2tf32(float x) {
    uint32_t r;
    asm("cvt.rna.tf32.f32 %0, %1;" : "=r"(r) : "f"(x));
    return r;
}

__device__ __forceinline__ void mma_tf32(float* c, const uint32_t* a, const uint32_t* b) {
    asm volatile(
        "mma.sync.aligned.m16n8k8.row.col.f32.tf32.tf32.f32 "
        "{%0,%1,%2,%3}, {%4,%5,%6,%7}, {%8,%9}, {%0,%1,%2,%3};"
        : "+f"(c[0]), "+f"(c[1]), "+f"(c[2]), "+f"(c[3])
        : "r"(a[0]), "r"(a[1]), "r"(a[2]), "r"(a[3]),
          "r"(b[0]), "r"(b[1]));
}

#define PITCH 136

// =================================================================================
// Kernel 1: QKV GEMM (verbatim from R2 — known good)
// =================================================================================
__global__ __launch_bounds__(256, 2) void qkv_gemm_tf32(
    const float* __restrict__ X, const float* __restrict__ W,
    const float* __restrict__ bias)
{
    __shared__ float Ah[16][PITCH], Al[16][PITCH];
    __shared__ float Bh[16][PITCH], Bl[16][PITCH];

    const int bn = blockIdx.x, bm = blockIdx.y;
    const int tid = threadIdx.x;
    const int warp = tid >> 5, lane = tid & 31;
    const int g = lane >> 2, tg = lane & 3;
    const int wm = (warp >> 2) * 64;
    const int wn = (warp & 3) * 32;
    const int row0 = bm * 128, col0 = bn * 128;

    float C[4][4][4];
#pragma unroll
    for (int mi = 0; mi < 4; mi++)
#pragma unroll
        for (int ni = 0; ni < 4; ni++)
#pragma unroll
            for (int t = 0; t < 4; t++) C[mi][ni][t] = 0.f;

    for (int k0 = 0; k0 < EE; k0 += 16) {
#pragma unroll
        for (int it = 0; it < 2; it++) {
            int f4 = tid + it * 256;
            int r = f4 >> 2;
            int c = (f4 & 3) << 2;
            float4 v = *(const float4*)(X + (size_t)(row0 + r) * EE + k0 + c);
            float xs[4] = {v.x, v.y, v.z, v.w};
#pragma unroll
            for (int j = 0; j < 4; j++) {
                float hf = __uint_as_float(f2tf32(xs[j]));
                Ah[c + j][r] = hf;
                Al[c + j][r] = xs[j] - hf;
            }
        }
#pragma unroll
        for (int it = 0; it < 2; it++) {
            int f4 = tid + it * 256;
            int kk = f4 >> 5;
            int c = (f4 & 31) << 2;
            float4 v = *(const float4*)(W + (size_t)(k0 + kk) * NQKV + col0 + c);
            float xs[4] = {v.x, v.y, v.z, v.w};
            float hf[4], lf[4];
#pragma unroll
            for (int j = 0; j < 4; j++) {
                hf[j] = __uint_as_float(f2tf32(xs[j]));
                lf[j] = xs[j] - hf[j];
            }
            *(float4*)&Bh[kk][c] = make_float4(hf[0], hf[1], hf[2], hf[3]);
            *(float4*)&Bl[kk][c] = make_float4(lf[0], lf[1], lf[2], lf[3]);
        }
        __syncthreads();

#pragma unroll
        for (int ks = 0; ks < 2; ks++) {
            const int kb = ks * 8;
            uint32_t ah[4][4], al[4][4], bh[4][2], bl[4][2];
#pragma unroll
            for (int mi = 0; mi < 4; mi++) {
                int m = wm + mi * 16 + g;
                ah[mi][0] = __float_as_uint(Ah[kb + tg][m]);
                ah[mi][1] = __float_as_uint(Ah[kb + tg][m + 8]);
                ah[mi][2] = __float_as_uint(Ah[kb + tg + 4][m]);
                ah[mi][3] = __float_as_uint(Ah[kb + tg + 4][m + 8]);
                al[mi][0] = __float_as_uint(Al[kb + tg][m]);
                al[mi][1] = __float_as_uint(Al[kb + tg][m + 8]);
                al[mi][2] = __float_as_uint(Al[kb + tg + 4][m]);
                al[mi][3] = __float_as_uint(Al[kb + tg + 4][m + 8]);
            }
#pragma unroll
            for (int ni = 0; ni < 4; ni++) {
                int n = wn + ni * 8 + g;
                bh[ni][0] = __float_as_uint(Bh[kb + tg][n]);
                bh[ni][1] = __float_as_uint(Bh[kb + tg + 4][n]);
                bl[ni][0] = __float_as_uint(Bl[kb + tg][n]);
                bl[ni][1] = __float_as_uint(Bl[kb + tg + 4][n]);
            }
#pragma unroll
            for (int mi = 0; mi < 4; mi++)
#pragma unroll
                for (int ni = 0; ni < 4; ni++) {
                    mma_tf32(C[mi][ni], ah[mi], bh[ni]);
                    mma_tf32(C[mi][ni], ah[mi], bl[ni]);
                    mma_tf32(C[mi][ni], al[mi], bh[ni]);
                }
        }
        __syncthreads();
    }

#pragma unroll
    for (int mi = 0; mi < 4; mi++) {
#pragma unroll
        for (int half = 0; half < 2; half++) {
            int r = row0 + wm + mi * 16 + g + half * 8;
            int b_ = r >> 11;
            int s  = r & 2047;
#pragma unroll
            for (int ni = 0; ni < 4; ni++) {
#pragma unroll
                for (int c01 = 0; c01 < 2; c01++) {
                    int n = col0 + wn + ni * 8 + 2 * tg + c01;
                    float v = C[mi][ni][half * 2 + c01] + bias[n];
                    int which = n >> 10;
                    int e = n & 1023;
                    int h = e >> 6, d = e & 63;
                    float* dst = (which == 0) ? g_q : (which == 1) ? g_k : g_v;
                    dst[(size_t)(((b_ * HH) + h) * SS + s) * DD + d] = v;
                }
            }
        }
    }
}

// =================================================================================
// Kernel 3: proj GEMM (verbatim from R2 — known good)
// =================================================================================
__global__ __launch_bounds__(256, 2) void proj_gemm_tf32(
    const float* __restrict__ W, const float* __restrict__ bias,
    float* __restrict__ out)
{
    __shared__ float Ah[16][PITCH], Al[16][PITCH];
    __shared__ float Bh[16][PITCH], Bl[16][PITCH];

    const int bn = blockIdx.x, bm = blockIdx.y;
    const int tid = threadIdx.x;
    const int warp = tid >> 5, lane = tid & 31;
    const int g = lane >> 2, tg = lane & 3;
    const int wm = (warp >> 2) * 64;
    const int wn = (warp & 3) * 32;
    const int row0 = bm * 128, col0 = bn * 128;

    float C[4][4][4];
#pragma unroll
    for (int mi = 0; mi < 4; mi++)
#pragma unroll
        for (int ni = 0; ni < 4; ni++)
#pragma unroll
            for (int t = 0; t < 4; t++) C[mi][ni][t] = 0.f;

    for (int k0 = 0; k0 < EE; k0 += 16) {
#pragma unroll
        for (int it = 0; it < 2; it++) {
            int f4 = tid + it * 256;
            int r = f4 >> 2;
            int c = (f4 & 3) << 2;
            float4 v = *(const float4*)(g_ctx + (size_t)(row0 + r) * EE + k0 + c);
            float xs[4] = {v.x, v.y, v.z, v.w};
#pragma unroll
            for (int j = 0; j < 4; j++) {
                float hf = __uint_as_float(f2tf32(xs[j]));
                Ah[c + j][r] = hf;
                Al[c + j][r] = xs[j] - hf;
            }
        }
#pragma unroll
        for (int it = 0; it < 2; it++) {
            int f4 = tid + it * 256;
            int kk = f4 >> 5;
            int c = (f4 & 31) << 2;
            float4 v = *(const float4*)(W + (size_t)(k0 + kk) * EE + col0 + c);
            float xs[4] = {v.x, v.y, v.z, v.w};
            float hf[4], lf[4];
#pragma unroll
            for (int j = 0; j < 4; j++) {
                hf[j] = __uint_as_float(f2tf32(xs[j]));
                lf[j] = xs[j] - hf[j];
            }
            *(float4*)&Bh[kk][c] = make_float4(hf[0], hf[1], hf[2], hf[3]);
            *(float4*)&Bl[kk][c] = make_float4(lf[0], lf[1], lf[2], lf[3]);
        }
        __syncthreads();

#pragma unroll
        for (int ks = 0; ks < 2; ks++) {
            const int kb = ks * 8;
            uint32_t ah[4][4], al[4][4], bh[4][2], bl[4][2];
#pragma unroll
            for (int mi = 0; mi < 4; mi++) {
                int m = wm + mi * 16 + g;
                ah[mi][0] = __float_as_uint(Ah[kb + tg][m]);
                ah[mi][1] = __float_as_uint(Ah[kb + tg][m + 8]);
                ah[mi][2] = __float_as_uint(Ah[kb + tg + 4][m]);
                ah[mi][3] = __float_as_uint(Ah[kb + tg + 4][m + 8]);
                al[mi][0] = __float_as_uint(Al[kb + tg][m]);
                al[mi][1] = __float_as_uint(Al[kb + tg][m + 8]);
                al[mi][2] = __float_as_uint(Al[kb + tg + 4][m]);
                al[mi][3] = __float_as_uint(Al[kb + tg + 4][m + 8]);
            }
#pragma unroll
            for (int ni = 0; ni < 4; ni++) {
                int n = wn + ni * 8 + g;
                bh[ni][0] = __float_as_uint(Bh[kb + tg][n]);
                bh[ni][1] = __float_as_uint(Bh[kb + tg + 4][n]);
                bl[ni][0] = __float_as_uint(Bl[kb + tg][n]);
                bl[ni][1] = __float_as_uint(Bl[kb + tg + 4][n]);
            }
#pragma unroll
            for (int mi = 0; mi < 4; mi++)
#pragma unroll
                for (int ni = 0; ni < 4; ni++) {
                    mma_tf32(C[mi][ni], ah[mi], bh[ni]);
                    mma_tf32(C[mi][ni], ah[mi], bl[ni]);
                    mma_tf32(C[mi][ni], al[mi], bh[ni]);
                }
        }
        __syncthreads();
    }

#pragma unroll
    for (int mi = 0; mi < 4; mi++) {
#pragma unroll
        for (int half = 0; half < 2; half++) {
            int r = row0 + wm + mi * 16 + g + half * 8;
#pragma unroll
            for (int ni = 0; ni < 4; ni++) {
#pragma unroll
                for (int c01 = 0; c01 < 2; c01++) {
                    int n = col0 + wn + ni * 8 + 2 * tg + c01;
                    out[(size_t)r * EE + n] = C[mi][ni][half * 2 + c01] + bias[n];
                }
            }
        }
    }
}

// =================================================================================
// Kernel 2: single-pass causal attention, fp32 FFMA engines (R1-proven),
// single-pass algorithm (R4-proven). Per (qb,h,b):
//   for each kb<=qb: score GEMM (128x128x64 FFMA), e=exp(s) (no max), write e to
//   attn_w + Ps, accumulate l_run and O += Ps@Vs. Then normalize O, publish row
//   sums, in-place rescale of attn_w + upper-triangle zero-fill.
// =================================================================================
#define QS_OFF 0
#define KS_OFF (64 * 132)                    // 8448
#define VS_OFF (KS_OFF + 64 * 132)           // 16896
#define PS_OFF (VS_OFF + 128 * 68)           // 25600
#define LS_OFF (PS_OFF + 128 * 132)          // 42496
#define SMEM_FLOATS (LS_OFF + 128)
#define SMEM_BYTES (SMEM_FLOATS * 4)         // 170496

extern __shared__ float smbuf[];

__global__ __launch_bounds__(256) void attn_kernel(float* __restrict__ attn_w)
{
    float* Qs = smbuf + QS_OFF;   // [64][132] d-major
    float* Ks = smbuf + KS_OFF;   // [64][132] d-major
    float* Vs = smbuf + VS_OFF;   // [128][68] row-major
    float* Ps = smbuf + PS_OFF;   // [128][132]
    float* Ls = smbuf + LS_OFF;   // [128] row sums

    const int qb = (int)gridDim.x - 1 - (int)blockIdx.x;   // heavy blocks first
    const int h = blockIdx.y, b = blockIdx.z;
    const int tid = threadIdx.x;
    const int tx = tid & 15, ty = tid >> 4;
    const float scale = 0.125f;

    const float* Qg = g_q + (size_t)((b * HH + h) * SS) * DD;
    const float* Kg = g_k + (size_t)((b * HH + h) * SS) * DD;
    const float* Vg = g_v + (size_t)((b * HH + h) * SS) * DD;

    // load Q block transposed: Qs[d][r]
#pragma unroll
    for (int it = 0; it < 8; it++) {
        int f4 = tid + it * 256;
        int r = f4 >> 4;
        int c = (f4 & 15) << 2;
        float4 v = *(const float4*)(Qg + (size_t)(qb * 128 + r) * DD + c);
        Qs[(c + 0) * 132 + r] = v.x; Qs[(c + 1) * 132 + r] = v.y;
        Qs[(c + 2) * 132 + r] = v.z; Qs[(c + 3) * 132 + r] = v.w;
    }

    float l_run[8];
#pragma unroll
    for (int i = 0; i < 8; i++) l_run[i] = 0.f;

    float accO[8][4];
#pragma unroll
    for (int i = 0; i < 8; i++)
#pragma unroll
        for (int j = 0; j < 4; j++) accO[i][j] = 0.f;

    const size_t wbase_bh = (size_t)(b * HH + h) * SS * SS;

    for (int kb = 0; kb <= qb; kb++) {
        __syncthreads();   // protect Ks/Vs/Ps from previous iteration (and Qs on first)
#pragma unroll
        for (int it = 0; it < 8; it++) {
            int f4 = tid + it * 256;
            int r = f4 >> 4;
            int c = (f4 & 15) << 2;
            float4 v = *(const float4*)(Kg + (size_t)(kb * 128 + r) * DD + c);
            Ks[(c + 0) * 132 + r] = v.x; Ks[(c + 1) * 132 + r] = v.y;
            Ks[(c + 2) * 132 + r] = v.z; Ks[(c + 3) * 132 + r] = v.w;
            *(float4*)&Vs[r * 68 + c] = *(const float4*)(Vg + (size_t)(kb * 128 + r) * DD + c);
        }
        __syncthreads();

        // score GEMM: 8x8 per thread
        float acc[8][8];
#pragma unroll
        for (int i = 0; i < 8; i++)
#pragma unroll
            for (int j = 0; j < 8; j++) acc[i][j] = 0.f;

#pragma unroll 8
        for (int d = 0; d < 64; d++) {
            float a[8], bb[8];
            *(float4*)(a)      = *(float4*)&Qs[d * 132 + ty * 4];
            *(float4*)(a + 4)  = *(float4*)&Qs[d * 132 + 64 + ty * 4];
            *(float4*)(bb)     = *(float4*)&Ks[d * 132 + tx * 4];
            *(float4*)(bb + 4) = *(float4*)&Ks[d * 132 + 64 + tx * 4];
#pragma unroll
            for (int i = 0; i < 8; i++)
#pragma unroll
                for (int j = 0; j < 8; j++) acc[i][j] += a[i] * bb[j];
        }

        // e = exp(s) (no max subtraction), write e to attn_w + Ps, accumulate l
        const bool diag = (kb == qb);
#pragma unroll
        for (int i = 0; i < 8; i++) {
            int r = ((i & 4) ? 64 : 0) + (ty << 2) + (i & 3);
            float p[8];
            float lsum = 0.f;
#pragma unroll
            for (int j = 0; j < 8; j++) {
                int c = ((j & 4) ? 64 : 0) + (tx << 2) + (j & 3);
                float sv = acc[i][j] * scale;
                float pv = (diag && c > r) ? 0.f : __expf(sv);
                p[j] = pv;
                lsum += pv;
                Ps[r * 132 + c] = pv;
            }
#pragma unroll
            for (int o = 1; o < 16; o <<= 1)
                lsum += __shfl_xor_sync(0xffffffffu, lsum, o);
            l_run[i] += lsum;
            size_t gb = wbase_bh + (size_t)(qb * 128 + r) * SS + kb * 128;
            *(float4*)(attn_w + gb + tx * 4)      = make_float4(p[0], p[1], p[2], p[3]);
            *(float4*)(attn_w + gb + 64 + tx * 4) = make_float4(p[4], p[5], p[6], p[7]);
        }
        __syncthreads();

        // O += Ps[128,128] @ Vs[128,64]
#pragma unroll 8
        for (int k = 0; k < 128; k++) {
            float bv[4];
            *(float4*)bv = *(float4*)&Vs[k * 68 + tx * 4];
#pragma unroll
            for (int i = 0; i < 8; i++) {
                int r = ((i & 4) ? 64 : 0) + (ty << 2) + (i & 3);
                float pv = Ps[r * 132 + k];
#pragma unroll
                for (int j = 0; j < 4; j++) accO[i][j] += pv * bv[j];
            }
        }
    }

    // publish row sums + write normalized O to g_ctx
#pragma unroll
    for (int i = 0; i < 8; i++) {
        int r = ((i & 4) ? 64 : 0) + (ty << 2) + (i & 3);
        if (tx == 0) Ls[r] = l_run[i];
        float inv = 1.f / l_run[i];
        int q = qb * 128 + r;
        size_t base = (size_t)(b * SS + q) * EE + h * 64 + tx * 4;
        *(float4*)&g_ctx[base] = make_float4(accO[i][0] * inv, accO[i][1] * inv,
                                             accO[i][2] * inv, accO[i][3] * inv);
    }
    __syncthreads();

    // rescale written region in place + zero-fill upper triangle
    const int lim = (qb + 1) * 128;
    for (int idx = tid; idx < 128 * 512; idx += 256) {
        int row = idx >> 9;
        int c = (idx & 511) << 2;
        size_t p = wbase_bh + (size_t)(qb * 128 + row) * SS + c;
        if (c < lim) {
            float inv = 1.f / Ls[row];
            float4 t = *(float4*)(attn_w + p);
            t.x *= inv; t.y *= inv; t.z *= inv; t.w *= inv;
            *(float4*)(attn_w + p) = t;
        } else {
            *(float4*)(attn_w + p) = make_float4(0.f, 0.f, 0.f, 0.f);
        }
    }
}

// =================================================================================
// launch
// =================================================================================
extern "C" void kernel_launch(void* const* d_in, const int* in_sizes, int n_in,
                              void* d_out, int out_size)
{
    const float* hs = (const float*)d_in[0];
    const float* aw = (const float*)d_in[1];
    const float* ab = (const float*)d_in[2];
    const float* pw = (const float*)d_in[3];
    const float* pb = (const float*)d_in[4];

    float* out      = (float*)d_out;
    float* attn_out = out;                       // [2,2048,1024]
    float* attn_w   = out + (size_t)MM * EE;     // [2,16,2048,2048]

    cudaFuncSetAttribute(attn_kernel, cudaFuncAttributeMaxDynamicSharedMemorySize,
                         SMEM_BYTES);

    qkv_gemm_tf32<<<dim3(NQKV / 128, MM / 128), 256>>>(hs, aw, ab);
    attn_kernel<<<dim3(SS / 128, HH, BB), 256, SMEM_BYTES>>>(attn_w);
    proj_gemm_tf32<<<dim3(EE / 128, MM / 128), 256>>>(pw, pb, attn_out);
}

// round 6
// speedup vs baseline: 1.6796x; 1.6542x over previous
#include <cuda_runtime.h>
#include <math.h>
#include <stdint.h>

// Problem dims
#define BB 2
#define SS 2048
#define EE 1024
#define HH 16
#define DD 64
#define MM (BB * SS)      // 4096 rows
#define NQKV (3 * EE)     // 3072

// ---------------- scratch (static device globals; no allocation) ----------------
__device__ float g_q[BB * HH * SS * DD];   // [B,H,S,D]
__device__ float g_k[BB * HH * SS * DD];
__device__ float g_v[BB * HH * SS * DD];
__device__ float g_ctx[MM * EE];           // [B,S,E]
__device__ float g_l[BB * HH * SS];        // row sums of exp(s)

// ---------------- tf32 helpers (R2-proven) ----------------
__device__ __forceinline__ uint32_t f2tf32(float x) {
    uint32_t r;
    asm("cvt.rna.tf32.f32 %0, %1;" : "=r"(r) : "f"(x));
    return r;
}

__device__ __forceinline__ void mma_tf32(float* c, const uint32_t* a, const uint32_t* b) {
    asm volatile(
        "mma.sync.aligned.m16n8k8.row.col.f32.tf32.tf32.f32 "
        "{%0,%1,%2,%3}, {%4,%5,%6,%7}, {%8,%9}, {%0,%1,%2,%3};"
        : "+f"(c[0]), "+f"(c[1]), "+f"(c[2]), "+f"(c[3])
        : "r"(a[0]), "r"(a[1]), "r"(a[2]), "r"(a[3]),
          "r"(b[0]), "r"(b[1]));
}

#define PITCH 136

// =================================================================================
// Kernel 1: QKV GEMM (verbatim from R2 — known good)
// =================================================================================
__global__ __launch_bounds__(256, 2) void qkv_gemm_tf32(
    const float* __restrict__ X, const float* __restrict__ W,
    const float* __restrict__ bias)
{
    __shared__ float Ah[16][PITCH], Al[16][PITCH];
    __shared__ float Bh[16][PITCH], Bl[16][PITCH];

    const int bn = blockIdx.x, bm = blockIdx.y;
    const int tid = threadIdx.x;
    const int warp = tid >> 5, lane = tid & 31;
    const int g = lane >> 2, tg = lane & 3;
    const int wm = (warp >> 2) * 64;
    const int wn = (warp & 3) * 32;
    const int row0 = bm * 128, col0 = bn * 128;

    float C[4][4][4];
#pragma unroll
    for (int mi = 0; mi < 4; mi++)
#pragma unroll
        for (int ni = 0; ni < 4; ni++)
#pragma unroll
            for (int t = 0; t < 4; t++) C[mi][ni][t] = 0.f;

    for (int k0 = 0; k0 < EE; k0 += 16) {
#pragma unroll
        for (int it = 0; it < 2; it++) {
            int f4 = tid + it * 256;
            int r = f4 >> 2;
            int c = (f4 & 3) << 2;
            float4 v = *(const float4*)(X + (size_t)(row0 + r) * EE + k0 + c);
            float xs[4] = {v.x, v.y, v.z, v.w};
#pragma unroll
            for (int j = 0; j < 4; j++) {
                float hf = __uint_as_float(f2tf32(xs[j]));
                Ah[c + j][r] = hf;
                Al[c + j][r] = xs[j] - hf;
            }
        }
#pragma unroll
        for (int it = 0; it < 2; it++) {
            int f4 = tid + it * 256;
            int kk = f4 >> 5;
            int c = (f4 & 31) << 2;
            float4 v = *(const float4*)(W + (size_t)(k0 + kk) * NQKV + col0 + c);
            float xs[4] = {v.x, v.y, v.z, v.w};
            float hf[4], lf[4];
#pragma unroll
            for (int j = 0; j < 4; j++) {
                hf[j] = __uint_as_float(f2tf32(xs[j]));
                lf[j] = xs[j] - hf[j];
            }
            *(float4*)&Bh[kk][c] = make_float4(hf[0], hf[1], hf[2], hf[3]);
            *(float4*)&Bl[kk][c] = make_float4(lf[0], lf[1], lf[2], lf[3]);
        }
        __syncthreads();

#pragma unroll
        for (int ks = 0; ks < 2; ks++) {
            const int kb = ks * 8;
            uint32_t ah[4][4], al[4][4], bh[4][2], bl[4][2];
#pragma unroll
            for (int mi = 0; mi < 4; mi++) {
                int m = wm + mi * 16 + g;
                ah[mi][0] = __float_as_uint(Ah[kb + tg][m]);
                ah[mi][1] = __float_as_uint(Ah[kb + tg][m + 8]);
                ah[mi][2] = __float_as_uint(Ah[kb + tg + 4][m]);
                ah[mi][3] = __float_as_uint(Ah[kb + tg + 4][m + 8]);
                al[mi][0] = __float_as_uint(Al[kb + tg][m]);
                al[mi][1] = __float_as_uint(Al[kb + tg][m + 8]);
                al[mi][2] = __float_as_uint(Al[kb + tg + 4][m]);
                al[mi][3] = __float_as_uint(Al[kb + tg + 4][m + 8]);
            }
#pragma unroll
            for (int ni = 0; ni < 4; ni++) {
                int n = wn + ni * 8 + g;
                bh[ni][0] = __float_as_uint(Bh[kb + tg][n]);
                bh[ni][1] = __float_as_uint(Bh[kb + tg + 4][n]);
                bl[ni][0] = __float_as_uint(Bl[kb + tg][n]);
                bl[ni][1] = __float_as_uint(Bl[kb + tg + 4][n]);
            }
#pragma unroll
            for (int mi = 0; mi < 4; mi++)
#pragma unroll
                for (int ni = 0; ni < 4; ni++) {
                    mma_tf32(C[mi][ni], ah[mi], bh[ni]);
                    mma_tf32(C[mi][ni], ah[mi], bl[ni]);
                    mma_tf32(C[mi][ni], al[mi], bh[ni]);
                }
        }
        __syncthreads();
    }

#pragma unroll
    for (int mi = 0; mi < 4; mi++) {
#pragma unroll
        for (int half = 0; half < 2; half++) {
            int r = row0 + wm + mi * 16 + g + half * 8;
            int b_ = r >> 11;
            int s  = r & 2047;
#pragma unroll
            for (int ni = 0; ni < 4; ni++) {
#pragma unroll
                for (int c01 = 0; c01 < 2; c01++) {
                    int n = col0 + wn + ni * 8 + 2 * tg + c01;
                    float v = C[mi][ni][half * 2 + c01] + bias[n];
                    int which = n >> 10;
                    int e = n & 1023;
                    int h = e >> 6, d = e & 63;
                    float* dst = (which == 0) ? g_q : (which == 1) ? g_k : g_v;
                    dst[(size_t)(((b_ * HH) + h) * SS + s) * DD + d] = v;
                }
            }
        }
    }
}

// =================================================================================
// Kernel 3: proj GEMM (verbatim from R2 — known good)
// =================================================================================
__global__ __launch_bounds__(256, 2) void proj_gemm_tf32(
    const float* __restrict__ W, const float* __restrict__ bias,
    float* __restrict__ out)
{
    __shared__ float Ah[16][PITCH], Al[16][PITCH];
    __shared__ float Bh[16][PITCH], Bl[16][PITCH];

    const int bn = blockIdx.x, bm = blockIdx.y;
    const int tid = threadIdx.x;
    const int warp = tid >> 5, lane = tid & 31;
    const int g = lane >> 2, tg = lane & 3;
    const int wm = (warp >> 2) * 64;
    const int wn = (warp & 3) * 32;
    const int row0 = bm * 128, col0 = bn * 128;

    float C[4][4][4];
#pragma unroll
    for (int mi = 0; mi < 4; mi++)
#pragma unroll
        for (int ni = 0; ni < 4; ni++)
#pragma unroll
            for (int t = 0; t < 4; t++) C[mi][ni][t] = 0.f;

    for (int k0 = 0; k0 < EE; k0 += 16) {
#pragma unroll
        for (int it = 0; it < 2; it++) {
            int f4 = tid + it * 256;
            int r = f4 >> 2;
            int c = (f4 & 3) << 2;
            float4 v = *(const float4*)(g_ctx + (size_t)(row0 + r) * EE + k0 + c);
            float xs[4] = {v.x, v.y, v.z, v.w};
#pragma unroll
            for (int j = 0; j < 4; j++) {
                float hf = __uint_as_float(f2tf32(xs[j]));
                Ah[c + j][r] = hf;
                Al[c + j][r] = xs[j] - hf;
            }
        }
#pragma unroll
        for (int it = 0; it < 2; it++) {
            int f4 = tid + it * 256;
            int kk = f4 >> 5;
            int c = (f4 & 31) << 2;
            float4 v = *(const float4*)(W + (size_t)(k0 + kk) * EE + col0 + c);
            float xs[4] = {v.x, v.y, v.z, v.w};
            float hf[4], lf[4];
#pragma unroll
            for (int j = 0; j < 4; j++) {
                hf[j] = __uint_as_float(f2tf32(xs[j]));
                lf[j] = xs[j] - hf[j];
            }
            *(float4*)&Bh[kk][c] = make_float4(hf[0], hf[1], hf[2], hf[3]);
            *(float4*)&Bl[kk][c] = make_float4(lf[0], lf[1], lf[2], lf[3]);
        }
        __syncthreads();

#pragma unroll
        for (int ks = 0; ks < 2; ks++) {
            const int kb = ks * 8;
            uint32_t ah[4][4], al[4][4], bh[4][2], bl[4][2];
#pragma unroll
            for (int mi = 0; mi < 4; mi++) {
                int m = wm + mi * 16 + g;
                ah[mi][0] = __float_as_uint(Ah[kb + tg][m]);
                ah[mi][1] = __float_as_uint(Ah[kb + tg][m + 8]);
                ah[mi][2] = __float_as_uint(Ah[kb + tg + 4][m]);
                ah[mi][3] = __float_as_uint(Ah[kb + tg + 4][m + 8]);
                al[mi][0] = __float_as_uint(Al[kb + tg][m]);
                al[mi][1] = __float_as_uint(Al[kb + tg][m + 8]);
                al[mi][2] = __float_as_uint(Al[kb + tg + 4][m]);
                al[mi][3] = __float_as_uint(Al[kb + tg + 4][m + 8]);
            }
#pragma unroll
            for (int ni = 0; ni < 4; ni++) {
                int n = wn + ni * 8 + g;
                bh[ni][0] = __float_as_uint(Bh[kb + tg][n]);
                bh[ni][1] = __float_as_uint(Bh[kb + tg + 4][n]);
                bl[ni][0] = __float_as_uint(Bl[kb + tg][n]);
                bl[ni][1] = __float_as_uint(Bl[kb + tg + 4][n]);
            }
#pragma unroll
            for (int mi = 0; mi < 4; mi++)
#pragma unroll
                for (int ni = 0; ni < 4; ni++) {
                    mma_tf32(C[mi][ni], ah[mi], bh[ni]);
                    mma_tf32(C[mi][ni], ah[mi], bl[ni]);
                    mma_tf32(C[mi][ni], al[mi], bh[ni]);
                }
        }
        __syncthreads();
    }

#pragma unroll
    for (int mi = 0; mi < 4; mi++) {
#pragma unroll
        for (int half = 0; half < 2; half++) {
            int r = row0 + wm + mi * 16 + g + half * 8;
#pragma unroll
            for (int ni = 0; ni < 4; ni++) {
#pragma unroll
                for (int c01 = 0; c01 < 2; c01++) {
                    int n = col0 + wn + ni * 8 + 2 * tg + c01;
                    out[(size_t)r * EE + n] = C[mi][ni][half * 2 + c01] + bias[n];
                }
            }
        }
    }
}

// =================================================================================
// Kernel 2: single-pass causal attention, tf32 MMA (R4-validated mappings),
// restructured score loop: ks-outer / 4-way nt-inner => 4 independent
// accumulator quads (breaks R4's 24-deep dependent MMA chains).
// Writes unnormalized e = exp(s) to attn_w; publishes row sums to g_l;
// normalization of attn_w happens in rescale_kernel.
// =================================================================================
#define OQH 0
#define OQL (OQH + 64 * 132)      // Q hi/lo [d][row]
#define OKH (OQL + 64 * 132)      // K hi/lo [d][key64]
#define OKL (OKH + 64 * 68)
#define OVH (OKL + 64 * 68)       // V hi/lo [key64][d]
#define OVL (OVH + 64 * 68)
#define OPS (OVL + 64 * 68)       // P [row128][key64]
#define ATT_FLOATS (OPS + 128 * 68)
#define ATT_SMEM (ATT_FLOATS * 4)

__global__ __launch_bounds__(256) void attn_kernel(float* __restrict__ attn_w)
{
    extern __shared__ float sm[];
    float* Qh = sm + OQH;
    float* Ql = sm + OQL;
    float* Kh = sm + OKH;
    float* Kl = sm + OKL;
    float* Vh = sm + OVH;
    float* Vl = sm + OVL;
    float* Ps = sm + OPS;

    const int qb = (int)gridDim.x - 1 - (int)blockIdx.x;   // heavy blocks first
    const int h = blockIdx.y, b = blockIdx.z;
    const int tid = threadIdx.x;
    const int warp = tid >> 5, lane = tid & 31;
    const int g = lane >> 2, tg = lane & 3;

    const float* Qg = g_q + ((size_t)(b * HH + h) * SS + qb * 128) * DD;
    const float* Kg = g_k + (size_t)(b * HH + h) * SS * DD;
    const float* Vg = g_v + (size_t)(b * HH + h) * SS * DD;

    // ---- stage Q (pre-scaled by 1/8), transposed split into Qh/Ql[d][row] ----
#pragma unroll
    for (int it = 0; it < 8; it++) {
        int f4 = tid + it * 256;
        int r = f4 >> 4, c = (f4 & 15) << 2;
        float4 v = *(const float4*)(Qg + r * 64 + c);
        float xs[4] = {v.x * 0.125f, v.y * 0.125f, v.z * 0.125f, v.w * 0.125f};
#pragma unroll
        for (int j = 0; j < 4; j++) {
            float hf = __uint_as_float(f2tf32(xs[j]));
            Qh[(c + j) * 132 + r] = hf;
            Ql[(c + j) * 132 + r] = xs[j] - hf;
        }
    }
    __syncthreads();

    // ---- Q A-frags, register resident ----
    uint32_t qa_h[8][4], qa_l[8][4];
    {
        int m = warp * 16 + g;
#pragma unroll
        for (int ks = 0; ks < 8; ks++) {
            qa_h[ks][0] = __float_as_uint(Qh[(ks * 8 + tg) * 132 + m]);
            qa_h[ks][1] = __float_as_uint(Qh[(ks * 8 + tg) * 132 + m + 8]);
            qa_h[ks][2] = __float_as_uint(Qh[(ks * 8 + tg + 4) * 132 + m]);
            qa_h[ks][3] = __float_as_uint(Qh[(ks * 8 + tg + 4) * 132 + m + 8]);
            qa_l[ks][0] = __float_as_uint(Ql[(ks * 8 + tg) * 132 + m]);
            qa_l[ks][1] = __float_as_uint(Ql[(ks * 8 + tg) * 132 + m + 8]);
            qa_l[ks][2] = __float_as_uint(Ql[(ks * 8 + tg + 4) * 132 + m]);
            qa_l[ks][3] = __float_as_uint(Ql[(ks * 8 + tg + 4) * 132 + m + 8]);
        }
    }

    float accO[8][4];
#pragma unroll
    for (int dt = 0; dt < 8; dt++)
#pragma unroll
        for (int t = 0; t < 4; t++) accO[dt][t] = 0.f;
    float l0 = 0.f, l1 = 0.f;

    const int rowL = warp * 16 + g;
    const int row0g = qb * 128 + rowL;
    const size_t wbase = (size_t)(b * HH + h) * SS * SS;
    const int nch = 2 * (qb + 1);

    for (int ch = 0; ch < nch; ch++) {
        __syncthreads();
        // ---- stage K chunk [d][key] and V chunk [key][d], split hi/lo ----
#pragma unroll
        for (int it = 0; it < 4; it++) {
            int f4 = tid + it * 256;
            int key = f4 >> 4, c = (f4 & 15) << 2;
            float4 kv = *(const float4*)(Kg + (size_t)(ch * 64 + key) * 64 + c);
            float xs[4] = {kv.x, kv.y, kv.z, kv.w};
#pragma unroll
            for (int j = 0; j < 4; j++) {
                float hf = __uint_as_float(f2tf32(xs[j]));
                Kh[(c + j) * 68 + key] = hf;
                Kl[(c + j) * 68 + key] = xs[j] - hf;
            }
            float4 vv = *(const float4*)(Vg + (size_t)(ch * 64 + key) * 64 + c);
            float vs[4] = {vv.x, vv.y, vv.z, vv.w};
            float vh[4], vl[4];
#pragma unroll
            for (int j = 0; j < 4; j++) {
                vh[j] = __uint_as_float(f2tf32(vs[j]));
                vl[j] = vs[j] - vh[j];
            }
            *(float4*)&Vh[key * 68 + c] = make_float4(vh[0], vh[1], vh[2], vh[3]);
            *(float4*)&Vl[key * 68 + c] = make_float4(vl[0], vl[1], vl[2], vl[3]);
        }
        __syncthreads();

        const bool masked = (ch >= 2 * qb);

        // ---- scores: 2 groups of 4 n-tiles, 4 independent accumulator quads ----
#pragma unroll 1
        for (int grp = 0; grp < 2; grp++) {
            float acc[4][4];
#pragma unroll
            for (int q = 0; q < 4; q++)
#pragma unroll
                for (int t = 0; t < 4; t++) acc[q][t] = 0.f;

#pragma unroll
            for (int ks = 0; ks < 8; ks++) {
#pragma unroll
                for (int q = 0; q < 4; q++) {
                    int n = (grp * 4 + q) * 8 + g;
                    uint32_t bh[2], bl[2];
                    bh[0] = __float_as_uint(Kh[(ks * 8 + tg) * 68 + n]);
                    bh[1] = __float_as_uint(Kh[(ks * 8 + tg + 4) * 68 + n]);
                    bl[0] = __float_as_uint(Kl[(ks * 8 + tg) * 68 + n]);
                    bl[1] = __float_as_uint(Kl[(ks * 8 + tg + 4) * 68 + n]);
                    mma_tf32(acc[q], qa_h[ks], bh);
                    mma_tf32(acc[q], qa_h[ks], bl);
                    mma_tf32(acc[q], qa_l[ks], bh);
                }
            }

#pragma unroll
            for (int q = 0; q < 4; q++) {
                int nt = grp * 4 + q;
                int colb = ch * 64 + nt * 8 + 2 * tg;
                float e0, e1, e2, e3;
                if (masked) {
                    e0 = (colb     <= row0g)     ? __expf(acc[q][0]) : 0.f;
                    e1 = (colb + 1 <= row0g)     ? __expf(acc[q][1]) : 0.f;
                    e2 = (colb     <= row0g + 8) ? __expf(acc[q][2]) : 0.f;
                    e3 = (colb + 1 <= row0g + 8) ? __expf(acc[q][3]) : 0.f;
                } else {
                    e0 = __expf(acc[q][0]); e1 = __expf(acc[q][1]);
                    e2 = __expf(acc[q][2]); e3 = __expf(acc[q][3]);
                }
                l0 += e0 + e1; l1 += e2 + e3;
                size_t base = wbase + (size_t)row0g * SS + colb;
                *(float2*)(attn_w + base) = make_float2(e0, e1);
                *(float2*)(attn_w + base + (size_t)8 * SS) = make_float2(e2, e3);
                int pc = nt * 8 + 2 * tg;
                *(float2*)&Ps[rowL * 68 + pc]       = make_float2(e0, e1);
                *(float2*)&Ps[(rowL + 8) * 68 + pc] = make_float2(e2, e3);
            }
        }
        __syncwarp();   // Ps rows are per-warp private

        // ---- O += P @ V (ks-outer / dt-inner: 8 independent accumulators) ----
#pragma unroll 1
        for (int ks = 0; ks < 8; ks++) {
            uint32_t pa[4];
            pa[0] = f2tf32(Ps[rowL * 68 + ks * 8 + tg]);
            pa[1] = f2tf32(Ps[(rowL + 8) * 68 + ks * 8 + tg]);
            pa[2] = f2tf32(Ps[rowL * 68 + ks * 8 + tg + 4]);
            pa[3] = f2tf32(Ps[(rowL + 8) * 68 + ks * 8 + tg + 4]);
#pragma unroll
            for (int dt = 0; dt < 8; dt++) {
                uint32_t bh[2], bl[2];
                bh[0] = __float_as_uint(Vh[(ks * 8 + tg) * 68 + dt * 8 + g]);
                bh[1] = __float_as_uint(Vh[(ks * 8 + tg + 4) * 68 + dt * 8 + g]);
                bl[0] = __float_as_uint(Vl[(ks * 8 + tg) * 68 + dt * 8 + g]);
                bl[1] = __float_as_uint(Vl[(ks * 8 + tg + 4) * 68 + dt * 8 + g]);
                mma_tf32(accO[dt], pa, bh);
                mma_tf32(accO[dt], pa, bl);
            }
        }
    }

    // ---- row sums across quad; publish to g_l; write normalized O ----
#pragma unroll
    for (int o = 1; o < 4; o <<= 1) {
        l0 += __shfl_xor_sync(0xffffffffu, l0, o);
        l1 += __shfl_xor_sync(0xffffffffu, l1, o);
    }
    if (tg == 0) {
        g_l[(size_t)(b * HH + h) * SS + row0g] = l0;
        g_l[(size_t)(b * HH + h) * SS + row0g + 8] = l1;
    }
    float inv0 = 1.f / l0, inv1 = 1.f / l1;

#pragma unroll
    for (int dt = 0; dt < 8; dt++) {
        int col = h * 64 + dt * 8 + 2 * tg;
        *(float2*)&g_ctx[(size_t)(b * SS + row0g) * EE + col] =
            make_float2(accO[dt][0] * inv0, accO[dt][1] * inv0);
        *(float2*)&g_ctx[(size_t)(b * SS + row0g + 8) * EE + col] =
            make_float2(accO[dt][2] * inv1, accO[dt][3] * inv1);
    }
}

// =================================================================================
// Kernel 2b: rescale attn_w rows by 1/l and zero-fill the causal upper triangle.
// One block per (b,h,row): 2048 cols, 256 threads x 2 float4 each.
// =================================================================================
__global__ __launch_bounds__(256) void rescale_kernel(float* __restrict__ attn_w)
{
    const int row = blockIdx.x;            // 0 .. B*H*S-1
    const int s = row & (SS - 1);          // query position within sequence
    const float inv = 1.f / g_l[row];
    const int lim = s + 1;                 // cols < lim are valid
    float* p = attn_w + (size_t)row * SS;

#pragma unroll
    for (int it = 0; it < 2; it++) {
        int c = (threadIdx.x + it * 256) << 2;
        float4 t;
        if (c + 3 < lim) {
            t = *(float4*)(p + c);
            t.x *= inv; t.y *= inv; t.z *= inv; t.w *= inv;
        } else if (c < lim) {
            t = *(float4*)(p + c);
            t.x = (c     < lim) ? t.x * inv : 0.f;
            t.y = (c + 1 < lim) ? t.y * inv : 0.f;
            t.z = (c + 2 < lim) ? t.z * inv : 0.f;
            t.w = (c + 3 < lim) ? t.w * inv : 0.f;
        } else {
            t = make_float4(0.f, 0.f, 0.f, 0.f);
        }
        *(float4*)(p + c) = t;
    }
}

// =================================================================================
// launch
// =================================================================================
extern "C" void kernel_launch(void* const* d_in, const int* in_sizes, int n_in,
                              void* d_out, int out_size)
{
    const float* hs = (const float*)d_in[0];
    const float* aw = (const float*)d_in[1];
    const float* ab = (const float*)d_in[2];
    const float* pw = (const float*)d_in[3];
    const float* pb = (const float*)d_in[4];

    float* out      = (float*)d_out;
    float* attn_out = out;                       // [2,2048,1024]
    float* attn_w   = out + (size_t)MM * EE;     // [2,16,2048,2048]

    cudaFuncSetAttribute(attn_kernel, cudaFuncAttributeMaxDynamicSharedMemorySize,
                         ATT_SMEM);

    qkv_gemm_tf32<<<dim3(NQKV / 128, MM / 128), 256>>>(hs, aw, ab);
    attn_kernel<<<dim3(SS / 128, HH, BB), 256, ATT_SMEM>>>(attn_w);
    rescale_kernel<<<BB * HH * SS, 256>>>(attn_w);
    proj_gemm_tf32<<<dim3(EE / 128, MM / 128), 256>>>(pw, pb, attn_out);
}

// round 7
// speedup vs baseline: 2.1646x; 1.2888x over previous
#include <cuda_runtime.h>
#include <cuda_bf16.h>
#include <math.h>
#include <stdint.h>

// Problem dims
#define BB 2
#define SS 2048
#define EE 1024
#define HH 16
#define DD 64
#define MM (BB * SS)      // 4096 rows
#define NQKV (3 * EE)     // 3072

// ---------------- scratch (static device globals; no allocation) ----------------
__device__ float g_q[BB * HH * SS * DD];   // [B,H,S,D]
__device__ float g_k[BB * HH * SS * DD];
__device__ float g_v[BB * HH * SS * DD];
__device__ float g_ctx[MM * EE];           // [B,S,E]
__device__ float g_l[BB * HH * SS];        // row sums of exp(s)

// ---------------- tf32 helpers (attention; R2/R6-proven) ----------------
__device__ __forceinline__ uint32_t f2tf32(float x) {
    uint32_t r;
    asm("cvt.rna.tf32.f32 %0, %1;" : "=r"(r) : "f"(x));
    return r;
}

__device__ __forceinline__ void mma_tf32(float* c, const uint32_t* a, const uint32_t* b) {
    asm volatile(
        "mma.sync.aligned.m16n8k8.row.col.f32.tf32.tf32.f32 "
        "{%0,%1,%2,%3}, {%4,%5,%6,%7}, {%8,%9}, {%0,%1,%2,%3};"
        : "+f"(c[0]), "+f"(c[1]), "+f"(c[2]), "+f"(c[3])
        : "r"(a[0]), "r"(a[1]), "r"(a[2]), "r"(a[3]),
          "r"(b[0]), "r"(b[1]));
}

// ---------------- bf16 helpers (GEMMs; R3 mapping, verified) ----------------
__device__ __forceinline__ void mma_bf16(float* c, const uint32_t* a, const uint32_t* b) {
    asm volatile(
        "mma.sync.aligned.m16n8k16.row.col.f32.bf16.bf16.f32 "
        "{%0,%1,%2,%3}, {%4,%5,%6,%7}, {%8,%9}, {%0,%1,%2,%3};"
        : "+f"(c[0]), "+f"(c[1]), "+f"(c[2]), "+f"(c[3])
        : "r"(a[0]), "r"(a[1]), "r"(a[2]), "r"(a[3]), "r"(b[0]), "r"(b[1]));
}

__device__ __forceinline__ void ldsm4(uint32_t& r0, uint32_t& r1, uint32_t& r2, uint32_t& r3,
                                      const void* p) {
    uint32_t a = (uint32_t)__cvta_generic_to_shared(p);
    asm volatile("ldmatrix.sync.aligned.m8n8.x4.shared.b16 {%0,%1,%2,%3}, [%4];"
                 : "=r"(r0), "=r"(r1), "=r"(r2), "=r"(r3) : "r"(a));
}

__device__ __forceinline__ void ldsm2t(uint32_t& r0, uint32_t& r1, const void* p) {
    uint32_t a = (uint32_t)__cvta_generic_to_shared(p);
    asm volatile("ldmatrix.sync.aligned.m8n8.x2.trans.shared.b16 {%0,%1}, [%2];"
                 : "=r"(r0), "=r"(r1) : "r"(a));
}

__device__ __forceinline__ void split2(float a, float b, uint32_t& h, uint32_t& l) {
    __nv_bfloat162 th, tl;
    th.x = __float2bfloat16_rn(a);
    th.y = __float2bfloat16_rn(b);
    tl.x = __float2bfloat16_rn(a - __bfloat162float(th.x));
    tl.y = __float2bfloat16_rn(b - __bfloat162float(th.y));
    h = *(uint32_t*)&th;
    l = *(uint32_t*)&tl;
}

#define AP 24    // A tile pitch (bf16) for [128][16]
#define BP 136   // B tile pitch (bf16) for [16][128]

// =================================================================================
// Kernel 1: QKV = X @ W + b, bf16 3-term, 128x128 block, BK=16, warp 64x32.
// B stored [k][n] -> ldsm2t(trans) correct; A [m][k] -> ldsm4 non-trans correct.
// =================================================================================
__global__ __launch_bounds__(256, 2) void qkv_gemm_bf16(
    const float* __restrict__ X, const float* __restrict__ W,
    const float* __restrict__ bias)
{
    __shared__ __nv_bfloat16 Ah[128 * AP], Al[128 * AP];
    __shared__ __nv_bfloat16 Bh[16 * BP],  Bl[16 * BP];

    const int bn = blockIdx.x, bm = blockIdx.y;
    const int tid = threadIdx.x;
    const int warp = tid >> 5, lane = tid & 31;
    const int g = lane >> 2, tg = lane & 3;
    const int wm = (warp >> 2) * 64, wn = (warp & 3) * 32;
    const int row0 = bm * 128, col0 = bn * 128;

    float C[4][4][4];
#pragma unroll
    for (int mi = 0; mi < 4; mi++)
#pragma unroll
        for (int ni = 0; ni < 4; ni++)
#pragma unroll
            for (int t = 0; t < 4; t++) C[mi][ni][t] = 0.f;

    for (int k0 = 0; k0 < EE; k0 += 16) {
#pragma unroll
        for (int it = 0; it < 2; it++) {
            int f4 = tid + it * 256;
            int r = f4 >> 2, c = (f4 & 3) << 2;
            float4 v = *(const float4*)(X + (size_t)(row0 + r) * EE + k0 + c);
            uint32_t h01, h23, l01, l23;
            split2(v.x, v.y, h01, l01); split2(v.z, v.w, h23, l23);
            *(uint2*)&Ah[r * AP + c] = make_uint2(h01, h23);
            *(uint2*)&Al[r * AP + c] = make_uint2(l01, l23);
        }
#pragma unroll
        for (int it = 0; it < 2; it++) {
            int f4 = tid + it * 256;
            int kk = f4 >> 5, c = (f4 & 31) << 2;
            float4 v = *(const float4*)(W + (size_t)(k0 + kk) * NQKV + col0 + c);
            uint32_t h01, h23, l01, l23;
            split2(v.x, v.y, h01, l01); split2(v.z, v.w, h23, l23);
            *(uint2*)&Bh[kk * BP + c] = make_uint2(h01, h23);
            *(uint2*)&Bl[kk * BP + c] = make_uint2(l01, l23);
        }
        __syncthreads();

        uint32_t a_h[4][4], a_l[4][4], b_h[4][2], b_l[4][2];
#pragma unroll
        for (int mi = 0; mi < 4; mi++) {
            int row = wm + mi * 16 + (lane & 15);
            int ko = (lane >> 4) << 3;
            ldsm4(a_h[mi][0], a_h[mi][1], a_h[mi][2], a_h[mi][3], &Ah[row * AP + ko]);
            ldsm4(a_l[mi][0], a_l[mi][1], a_l[mi][2], a_l[mi][3], &Al[row * AP + ko]);
        }
#pragma unroll
        for (int ni = 0; ni < 4; ni++) {
            int kr = (lane & 7) + (lane & 8);
            int nc = wn + ni * 8;
            ldsm2t(b_h[ni][0], b_h[ni][1], &Bh[kr * BP + nc]);
            ldsm2t(b_l[ni][0], b_l[ni][1], &Bl[kr * BP + nc]);
        }
#pragma unroll
        for (int mi = 0; mi < 4; mi++)
#pragma unroll
            for (int ni = 0; ni < 4; ni++) {
                mma_bf16(C[mi][ni], a_h[mi], b_h[ni]);
                mma_bf16(C[mi][ni], a_h[mi], b_l[ni]);
                mma_bf16(C[mi][ni], a_l[mi], b_h[ni]);
            }
        __syncthreads();
    }

    // epilogue: bias + scatter to [B,H,S,D]
#pragma unroll
    for (int mi = 0; mi < 4; mi++) {
#pragma unroll
        for (int half = 0; half < 2; half++) {
            int r = row0 + wm + mi * 16 + g + half * 8;
            int b_ = r >> 11, s = r & 2047;
#pragma unroll
            for (int ni = 0; ni < 4; ni++) {
#pragma unroll
                for (int c01 = 0; c01 < 2; c01++) {
                    int n = col0 + wn + ni * 8 + 2 * tg + c01;
                    float v = C[mi][ni][half * 2 + c01] + bias[n];
                    int which = n >> 10;
                    int e = n & 1023;
                    int hh = e >> 6, d = e & 63;
                    float* dst = (which == 0) ? g_q : (which == 1) ? g_k : g_v;
                    dst[(size_t)(((b_ * HH) + hh) * SS + s) * DD + d] = v;
                }
            }
        }
    }
}

// =================================================================================
// Kernel 3: proj GEMM, bf16 3-term (same structure)
// =================================================================================
__global__ __launch_bounds__(256, 2) void proj_gemm_bf16(
    const float* __restrict__ W, const float* __restrict__ bias,
    float* __restrict__ out)
{
    __shared__ __nv_bfloat16 Ah[128 * AP], Al[128 * AP];
    __shared__ __nv_bfloat16 Bh[16 * BP],  Bl[16 * BP];

    const int bn = blockIdx.x, bm = blockIdx.y;
    const int tid = threadIdx.x;
    const int warp = tid >> 5, lane = tid & 31;
    const int g = lane >> 2, tg = lane & 3;
    const int wm = (warp >> 2) * 64, wn = (warp & 3) * 32;
    const int row0 = bm * 128, col0 = bn * 128;

    float C[4][4][4];
#pragma unroll
    for (int mi = 0; mi < 4; mi++)
#pragma unroll
        for (int ni = 0; ni < 4; ni++)
#pragma unroll
            for (int t = 0; t < 4; t++) C[mi][ni][t] = 0.f;

    for (int k0 = 0; k0 < EE; k0 += 16) {
#pragma unroll
        for (int it = 0; it < 2; it++) {
            int f4 = tid + it * 256;
            int r = f4 >> 2, c = (f4 & 3) << 2;
            float4 v = *(const float4*)(g_ctx + (size_t)(row0 + r) * EE + k0 + c);
            uint32_t h01, h23, l01, l23;
            split2(v.x, v.y, h01, l01); split2(v.z, v.w, h23, l23);
            *(uint2*)&Ah[r * AP + c] = make_uint2(h01, h23);
            *(uint2*)&Al[r * AP + c] = make_uint2(l01, l23);
        }
#pragma unroll
        for (int it = 0; it < 2; it++) {
            int f4 = tid + it * 256;
            int kk = f4 >> 5, c = (f4 & 31) << 2;
            float4 v = *(const float4*)(W + (size_t)(k0 + kk) * EE + col0 + c);
            uint32_t h01, h23, l01, l23;
            split2(v.x, v.y, h01, l01); split2(v.z, v.w, h23, l23);
            *(uint2*)&Bh[kk * BP + c] = make_uint2(h01, h23);
            *(uint2*)&Bl[kk * BP + c] = make_uint2(l01, l23);
        }
        __syncthreads();

        uint32_t a_h[4][4], a_l[4][4], b_h[4][2], b_l[4][2];
#pragma unroll
        for (int mi = 0; mi < 4; mi++) {
            int row = wm + mi * 16 + (lane & 15);
            int ko = (lane >> 4) << 3;
            ldsm4(a_h[mi][0], a_h[mi][1], a_h[mi][2], a_h[mi][3], &Ah[row * AP + ko]);
            ldsm4(a_l[mi][0], a_l[mi][1], a_l[mi][2], a_l[mi][3], &Al[row * AP + ko]);
        }
#pragma unroll
        for (int ni = 0; ni < 4; ni++) {
            int kr = (lane & 7) + (lane & 8);
            int nc = wn + ni * 8;
            ldsm2t(b_h[ni][0], b_h[ni][1], &Bh[kr * BP + nc]);
            ldsm2t(b_l[ni][0], b_l[ni][1], &Bl[kr * BP + nc]);
        }
#pragma unroll
        for (int mi = 0; mi < 4; mi++)
#pragma unroll
            for (int ni = 0; ni < 4; ni++) {
                mma_bf16(C[mi][ni], a_h[mi], b_h[ni]);
                mma_bf16(C[mi][ni], a_h[mi], b_l[ni]);
                mma_bf16(C[mi][ni], a_l[mi], b_h[ni]);
            }
        __syncthreads();
    }

#pragma unroll
    for (int mi = 0; mi < 4; mi++) {
#pragma unroll
        for (int half = 0; half < 2; half++) {
            int r = row0 + wm + mi * 16 + g + half * 8;
#pragma unroll
            for (int ni = 0; ni < 4; ni++) {
#pragma unroll
                for (int c01 = 0; c01 < 2; c01++) {
                    int n = col0 + wn + ni * 8 + 2 * tg + c01;
                    out[(size_t)r * EE + n] = C[mi][ni][half * 2 + c01] + bias[n];
                }
            }
        }
    }
}

// =================================================================================
// Kernel 2: single-pass causal attention, tf32 MMA (verbatim from R6 — known good)
// =================================================================================
#define OQH 0
#define OQL (OQH + 64 * 132)
#define OKH (OQL + 64 * 132)
#define OKL (OKH + 64 * 68)
#define OVH (OKL + 64 * 68)
#define OVL (OVH + 64 * 68)
#define OPS (OVL + 64 * 68)
#define ATT_FLOATS (OPS + 128 * 68)
#define ATT_SMEM (ATT_FLOATS * 4)

__global__ __launch_bounds__(256) void attn_kernel(float* __restrict__ attn_w)
{
    extern __shared__ float sm[];
    float* Qh = sm + OQH;
    float* Ql = sm + OQL;
    float* Kh = sm + OKH;
    float* Kl = sm + OKL;
    float* Vh = sm + OVH;
    float* Vl = sm + OVL;
    float* Ps = sm + OPS;

    const int qb = (int)gridDim.x - 1 - (int)blockIdx.x;
    const int h = blockIdx.y, b = blockIdx.z;
    const int tid = threadIdx.x;
    const int warp = tid >> 5, lane = tid & 31;
    const int g = lane >> 2, tg = lane & 3;

    const float* Qg = g_q + ((size_t)(b * HH + h) * SS + qb * 128) * DD;
    const float* Kg = g_k + (size_t)(b * HH + h) * SS * DD;
    const float* Vg = g_v + (size_t)(b * HH + h) * SS * DD;

#pragma unroll
    for (int it = 0; it < 8; it++) {
        int f4 = tid + it * 256;
        int r = f4 >> 4, c = (f4 & 15) << 2;
        float4 v = *(const float4*)(Qg + r * 64 + c);
        float xs[4] = {v.x * 0.125f, v.y * 0.125f, v.z * 0.125f, v.w * 0.125f};
#pragma unroll
        for (int j = 0; j < 4; j++) {
            float hf = __uint_as_float(f2tf32(xs[j]));
            Qh[(c + j) * 132 + r] = hf;
            Ql[(c + j) * 132 + r] = xs[j] - hf;
        }
    }
    __syncthreads();

    uint32_t qa_h[8][4], qa_l[8][4];
    {
        int m = warp * 16 + g;
#pragma unroll
        for (int ks = 0; ks < 8; ks++) {
            qa_h[ks][0] = __float_as_uint(Qh[(ks * 8 + tg) * 132 + m]);
            qa_h[ks][1] = __float_as_uint(Qh[(ks * 8 + tg) * 132 + m + 8]);
            qa_h[ks][2] = __float_as_uint(Qh[(ks * 8 + tg + 4) * 132 + m]);
            qa_h[ks][3] = __float_as_uint(Qh[(ks * 8 + tg + 4) * 132 + m + 8]);
            qa_l[ks][0] = __float_as_uint(Ql[(ks * 8 + tg) * 132 + m]);
            qa_l[ks][1] = __float_as_uint(Ql[(ks * 8 + tg) * 132 + m + 8]);
            qa_l[ks][2] = __float_as_uint(Ql[(ks * 8 + tg + 4) * 132 + m]);
            qa_l[ks][3] = __float_as_uint(Ql[(ks * 8 + tg + 4) * 132 + m + 8]);
        }
    }

    float accO[8][4];
#pragma unroll
    for (int dt = 0; dt < 8; dt++)
#pragma unroll
        for (int t = 0; t < 4; t++) accO[dt][t] = 0.f;
    float l0 = 0.f, l1 = 0.f;

    const int rowL = warp * 16 + g;
    const int row0g = qb * 128 + rowL;
    const size_t wbase = (size_t)(b * HH + h) * SS * SS;
    const int nch = 2 * (qb + 1);

    for (int ch = 0; ch < nch; ch++) {
        __syncthreads();
#pragma unroll
        for (int it = 0; it < 4; it++) {
            int f4 = tid + it * 256;
            int key = f4 >> 4, c = (f4 & 15) << 2;
            float4 kv = *(const float4*)(Kg + (size_t)(ch * 64 + key) * 64 + c);
            float xs[4] = {kv.x, kv.y, kv.z, kv.w};
#pragma unroll
            for (int j = 0; j < 4; j++) {
                float hf = __uint_as_float(f2tf32(xs[j]));
                Kh[(c + j) * 68 + key] = hf;
                Kl[(c + j) * 68 + key] = xs[j] - hf;
            }
            float4 vv = *(const float4*)(Vg + (size_t)(ch * 64 + key) * 64 + c);
            float vs[4] = {vv.x, vv.y, vv.z, vv.w};
            float vh[4], vl[4];
#pragma unroll
            for (int j = 0; j < 4; j++) {
                vh[j] = __uint_as_float(f2tf32(vs[j]));
                vl[j] = vs[j] - vh[j];
            }
            *(float4*)&Vh[key * 68 + c] = make_float4(vh[0], vh[1], vh[2], vh[3]);
            *(float4*)&Vl[key * 68 + c] = make_float4(vl[0], vl[1], vl[2], vl[3]);
        }
        __syncthreads();

        const bool masked = (ch >= 2 * qb);

#pragma unroll 1
        for (int grp = 0; grp < 2; grp++) {
            float acc[4][4];
#pragma unroll
            for (int q = 0; q < 4; q++)
#pragma unroll
                for (int t = 0; t < 4; t++) acc[q][t] = 0.f;

#pragma unroll
            for (int ks = 0; ks < 8; ks++) {
#pragma unroll
                for (int q = 0; q < 4; q++) {
                    int n = (grp * 4 + q) * 8 + g;
                    uint32_t bh[2], bl[2];
                    bh[0] = __float_as_uint(Kh[(ks * 8 + tg) * 68 + n]);
                    bh[1] = __float_as_uint(Kh[(ks * 8 + tg + 4) * 68 + n]);
                    bl[0] = __float_as_uint(Kl[(ks * 8 + tg) * 68 + n]);
                    bl[1] = __float_as_uint(Kl[(ks * 8 + tg + 4) * 68 + n]);
                    mma_tf32(acc[q], qa_h[ks], bh);
                    mma_tf32(acc[q], qa_h[ks], bl);
                    mma_tf32(acc[q], qa_l[ks], bh);
                }
            }

#pragma unroll
            for (int q = 0; q < 4; q++) {
                int nt = grp * 4 + q;
                int colb = ch * 64 + nt * 8 + 2 * tg;
                float e0, e1, e2, e3;
                if (masked) {
                    e0 = (colb     <= row0g)     ? __expf(acc[q][0]) : 0.f;
                    e1 = (colb + 1 <= row0g)     ? __expf(acc[q][1]) : 0.f;
                    e2 = (colb     <= row0g + 8) ? __expf(acc[q][2]) : 0.f;
                    e3 = (colb + 1 <= row0g + 8) ? __expf(acc[q][3]) : 0.f;
                } else {
                    e0 = __expf(acc[q][0]); e1 = __expf(acc[q][1]);
                    e2 = __expf(acc[q][2]); e3 = __expf(acc[q][3]);
                }
                l0 += e0 + e1; l1 += e2 + e3;
                size_t base = wbase + (size_t)row0g * SS + colb;
                *(float2*)(attn_w + base) = make_float2(e0, e1);
                *(float2*)(attn_w + base + (size_t)8 * SS) = make_float2(e2, e3);
                int pc = nt * 8 + 2 * tg;
                *(float2*)&Ps[rowL * 68 + pc]       = make_float2(e0, e1);
                *(float2*)&Ps[(rowL + 8) * 68 + pc] = make_float2(e2, e3);
            }
        }
        __syncwarp();

#pragma unroll 1
        for (int ks = 0; ks < 8; ks++) {
            uint32_t pa[4];
            pa[0] = f2tf32(Ps[rowL * 68 + ks * 8 + tg]);
            pa[1] = f2tf32(Ps[(rowL + 8) * 68 + ks * 8 + tg]);
            pa[2] = f2tf32(Ps[rowL * 68 + ks * 8 + tg + 4]);
            pa[3] = f2tf32(Ps[(rowL + 8) * 68 + ks * 8 + tg + 4]);
#pragma unroll
            for (int dt = 0; dt < 8; dt++) {
                uint32_t bh[2], bl[2];
                bh[0] = __float_as_uint(Vh[(ks * 8 + tg) * 68 + dt * 8 + g]);
                bh[1] = __float_as_uint(Vh[(ks * 8 + tg + 4) * 68 + dt * 8 + g]);
                bl[0] = __float_as_uint(Vl[(ks * 8 + tg) * 68 + dt * 8 + g]);
                bl[1] = __float_as_uint(Vl[(ks * 8 + tg + 4) * 68 + dt * 8 + g]);
                mma_tf32(accO[dt], pa, bh);
                mma_tf32(accO[dt], pa, bl);
            }
        }
    }

#pragma unroll
    for (int o = 1; o < 4; o <<= 1) {
        l0 += __shfl_xor_sync(0xffffffffu, l0, o);
        l1 += __shfl_xor_sync(0xffffffffu, l1, o);
    }
    if (tg == 0) {
        g_l[(size_t)(b * HH + h) * SS + row0g] = l0;
        g_l[(size_t)(b * HH + h) * SS + row0g + 8] = l1;
    }
    float inv0 = 1.f / l0, inv1 = 1.f / l1;

#pragma unroll
    for (int dt = 0; dt < 8; dt++) {
        int col = h * 64 + dt * 8 + 2 * tg;
        *(float2*)&g_ctx[(size_t)(b * SS + row0g) * EE + col] =
            make_float2(accO[dt][0] * inv0, accO[dt][1] * inv0);
        *(float2*)&g_ctx[(size_t)(b * SS + row0g + 8) * EE + col] =
            make_float2(accO[dt][2] * inv1, accO[dt][3] * inv1);
    }
}

// =================================================================================
// Kernel 2b: rescale + zero-fill (verbatim from R6 — known good)
// =================================================================================
__global__ __launch_bounds__(256) void rescale_kernel(float* __restrict__ attn_w)
{
    const int row = blockIdx.x;
    const int s = row & (SS - 1);
    const float inv = 1.f / g_l[row];
    const int lim = s + 1;
    float* p = attn_w + (size_t)row * SS;

#pragma unroll
    for (int it = 0; it < 2; it++) {
        int c = (threadIdx.x + it * 256) << 2;
        float4 t;
        if (c + 3 < lim) {
            t = *(float4*)(p + c);
            t.x *= inv; t.y *= inv; t.z *= inv; t.w *= inv;
        } else if (c < lim) {
            t = *(float4*)(p + c);
            t.x = (c     < lim) ? t.x * inv : 0.f;
            t.y = (c + 1 < lim) ? t.y * inv : 0.f;
            t.z = (c + 2 < lim) ? t.z * inv : 0.f;
            t.w = (c + 3 < lim) ? t.w * inv : 0.f;
        } else {
            t = make_float4(0.f, 0.f, 0.f, 0.f);
        }
        *(float4*)(p + c) = t;
    }
}

// =================================================================================
// launch
// =================================================================================
extern "C" void kernel_launch(void* const* d_in, const int* in_sizes, int n_in,
                              void* d_out, int out_size)
{
    const float* hs = (const float*)d_in[0];
    const float* aw = (const float*)d_in[1];
    const float* ab = (const float*)d_in[2];
    const float* pw = (const float*)d_in[3];
    const float* pb = (const float*)d_in[4];

    float* out      = (float*)d_out;
    float* attn_out = out;                       // [2,2048,1024]
    float* attn_w   = out + (size_t)MM * EE;     // [2,16,2048,2048]

    cudaFuncSetAttribute(attn_kernel, cudaFuncAttributeMaxDynamicSharedMemorySize,
                         ATT_SMEM);

    qkv_gemm_bf16<<<dim3(NQKV / 128, MM / 128), 256>>>(hs, aw, ab);
    attn_kernel<<<dim3(SS / 128, HH, BB), 256, ATT_SMEM>>>(attn_w);
    rescale_kernel<<<BB * HH * SS, 256>>>(attn_w);
    proj_gemm_bf16<<<dim3(EE / 128, MM / 128), 256>>>(pw, pb, attn_out);
}

// round 8
// speedup vs baseline: 3.1476x; 1.4541x over previous
#include <cuda_runtime.h>
#include <cuda_bf16.h>
#include <math.h>
#include <stdint.h>

// Problem dims
#define BB 2
#define SS 2048
#define EE 1024
#define HH 16
#define DD 64
#define MM (BB * SS)      // 4096
#define NQKV (3 * EE)     // 3072

// ---------------- scratch ----------------
__device__ float g_q[BB * HH * SS * DD];   // [B,H,S,D]
__device__ float g_k[BB * HH * SS * DD];
__device__ float g_v[BB * HH * SS * DD];
__device__ float g_ctx[MM * EE];           // [B,S,E]
__device__ float g_l[BB * HH * SS];        // row sums of exp(s)

// ---------------- bf16 helpers ----------------
__device__ __forceinline__ void mma_bf16(float* c, const uint32_t* a, const uint32_t* b) {
    asm volatile(
        "mma.sync.aligned.m16n8k16.row.col.f32.bf16.bf16.f32 "
        "{%0,%1,%2,%3}, {%4,%5,%6,%7}, {%8,%9}, {%0,%1,%2,%3};"
        : "+f"(c[0]), "+f"(c[1]), "+f"(c[2]), "+f"(c[3])
        : "r"(a[0]), "r"(a[1]), "r"(a[2]), "r"(a[3]), "r"(b[0]), "r"(b[1]));
}

__device__ __forceinline__ void ldsm4(uint32_t& r0, uint32_t& r1, uint32_t& r2, uint32_t& r3,
                                      const void* p) {
    uint32_t a = (uint32_t)__cvta_generic_to_shared(p);
    asm volatile("ldmatrix.sync.aligned.m8n8.x4.shared.b16 {%0,%1,%2,%3}, [%4];"
                 : "=r"(r0), "=r"(r1), "=r"(r2), "=r"(r3) : "r"(a));
}

__device__ __forceinline__ void ldsm2t(uint32_t& r0, uint32_t& r1, const void* p) {
    uint32_t a = (uint32_t)__cvta_generic_to_shared(p);
    asm volatile("ldmatrix.sync.aligned.m8n8.x2.trans.shared.b16 {%0,%1}, [%2];"
                 : "=r"(r0), "=r"(r1) : "r"(a));
}

// split two floats into packed bf16 hi + bf16 lo residual
__device__ __forceinline__ void split2(float a, float b, uint32_t& h, uint32_t& l) {
    __nv_bfloat162 th, tl;
    th.x = __float2bfloat16_rn(a);
    th.y = __float2bfloat16_rn(b);
    tl.x = __float2bfloat16_rn(a - __bfloat162float(th.x));
    tl.y = __float2bfloat16_rn(b - __bfloat162float(th.y));
    h = *(uint32_t*)&th;
    l = *(uint32_t*)&tl;
}

#define AP 24
#define BP 136

// =================================================================================
// Kernel 1: QKV GEMM, bf16 3-term (verbatim from R7 — known good)
// =================================================================================
__global__ __launch_bounds__(256, 2) void qkv_gemm_bf16(
    const float* __restrict__ X, const float* __restrict__ W,
    const float* __restrict__ bias)
{
    __shared__ __nv_bfloat16 Ah[128 * AP], Al[128 * AP];
    __shared__ __nv_bfloat16 Bh[16 * BP],  Bl[16 * BP];

    const int bn = blockIdx.x, bm = blockIdx.y;
    const int tid = threadIdx.x;
    const int warp = tid >> 5, lane = tid & 31;
    const int g = lane >> 2, tg = lane & 3;
    const int wm = (warp >> 2) * 64, wn = (warp & 3) * 32;
    const int row0 = bm * 128, col0 = bn * 128;

    float C[4][4][4];
#pragma unroll
    for (int mi = 0; mi < 4; mi++)
#pragma unroll
        for (int ni = 0; ni < 4; ni++)
#pragma unroll
            for (int t = 0; t < 4; t++) C[mi][ni][t] = 0.f;

    for (int k0 = 0; k0 < EE; k0 += 16) {
#pragma unroll
        for (int it = 0; it < 2; it++) {
            int f4 = tid + it * 256;
            int r = f4 >> 2, c = (f4 & 3) << 2;
            float4 v = *(const float4*)(X + (size_t)(row0 + r) * EE + k0 + c);
            uint32_t h01, h23, l01, l23;
            split2(v.x, v.y, h01, l01); split2(v.z, v.w, h23, l23);
            *(uint2*)&Ah[r * AP + c] = make_uint2(h01, h23);
            *(uint2*)&Al[r * AP + c] = make_uint2(l01, l23);
        }
#pragma unroll
        for (int it = 0; it < 2; it++) {
            int f4 = tid + it * 256;
            int kk = f4 >> 5, c = (f4 & 31) << 2;
            float4 v = *(const float4*)(W + (size_t)(k0 + kk) * NQKV + col0 + c);
            uint32_t h01, h23, l01, l23;
            split2(v.x, v.y, h01, l01); split2(v.z, v.w, h23, l23);
            *(uint2*)&Bh[kk * BP + c] = make_uint2(h01, h23);
            *(uint2*)&Bl[kk * BP + c] = make_uint2(l01, l23);
        }
        __syncthreads();

        uint32_t a_h[4][4], a_l[4][4], b_h[4][2], b_l[4][2];
#pragma unroll
        for (int mi = 0; mi < 4; mi++) {
            int row = wm + mi * 16 + (lane & 15);
            int ko = (lane >> 4) << 3;
            ldsm4(a_h[mi][0], a_h[mi][1], a_h[mi][2], a_h[mi][3], &Ah[row * AP + ko]);
            ldsm4(a_l[mi][0], a_l[mi][1], a_l[mi][2], a_l[mi][3], &Al[row * AP + ko]);
        }
#pragma unroll
        for (int ni = 0; ni < 4; ni++) {
            int kr = (lane & 7) + (lane & 8);
            int nc = wn + ni * 8;
            ldsm2t(b_h[ni][0], b_h[ni][1], &Bh[kr * BP + nc]);
            ldsm2t(b_l[ni][0], b_l[ni][1], &Bl[kr * BP + nc]);
        }
#pragma unroll
        for (int mi = 0; mi < 4; mi++)
#pragma unroll
            for (int ni = 0; ni < 4; ni++) {
                mma_bf16(C[mi][ni], a_h[mi], b_h[ni]);
                mma_bf16(C[mi][ni], a_h[mi], b_l[ni]);
                mma_bf16(C[mi][ni], a_l[mi], b_h[ni]);
            }
        __syncthreads();
    }

#pragma unroll
    for (int mi = 0; mi < 4; mi++) {
#pragma unroll
        for (int half = 0; half < 2; half++) {
            int r = row0 + wm + mi * 16 + g + half * 8;
            int b_ = r >> 11, s = r & 2047;
#pragma unroll
            for (int ni = 0; ni < 4; ni++) {
#pragma unroll
                for (int c01 = 0; c01 < 2; c01++) {
                    int n = col0 + wn + ni * 8 + 2 * tg + c01;
                    float v = C[mi][ni][half * 2 + c01] + bias[n];
                    int which = n >> 10;
                    int e = n & 1023;
                    int hh = e >> 6, d = e & 63;
                    float* dst = (which == 0) ? g_q : (which == 1) ? g_k : g_v;
                    dst[(size_t)(((b_ * HH) + hh) * SS + s) * DD + d] = v;
                }
            }
        }
    }
}

// =================================================================================
// Kernel 3: proj GEMM, bf16 3-term (verbatim from R7 — known good)
// =================================================================================
__global__ __launch_bounds__(256, 2) void proj_gemm_bf16(
    const float* __restrict__ W, const float* __restrict__ bias,
    float* __restrict__ out)
{
    __shared__ __nv_bfloat16 Ah[128 * AP], Al[128 * AP];
    __shared__ __nv_bfloat16 Bh[16 * BP],  Bl[16 * BP];

    const int bn = blockIdx.x, bm = blockIdx.y;
    const int tid = threadIdx.x;
    const int warp = tid >> 5, lane = tid & 31;
    const int g = lane >> 2, tg = lane & 3;
    const int wm = (warp >> 2) * 64, wn = (warp & 3) * 32;
    const int row0 = bm * 128, col0 = bn * 128;

    float C[4][4][4];
#pragma unroll
    for (int mi = 0; mi < 4; mi++)
#pragma unroll
        for (int ni = 0; ni < 4; ni++)
#pragma unroll
            for (int t = 0; t < 4; t++) C[mi][ni][t] = 0.f;

    for (int k0 = 0; k0 < EE; k0 += 16) {
#pragma unroll
        for (int it = 0; it < 2; it++) {
            int f4 = tid + it * 256;
            int r = f4 >> 2, c = (f4 & 3) << 2;
            float4 v = *(const float4*)(g_ctx + (size_t)(row0 + r) * EE + k0 + c);
            uint32_t h01, h23, l01, l23;
            split2(v.x, v.y, h01, l01); split2(v.z, v.w, h23, l23);
            *(uint2*)&Ah[r * AP + c] = make_uint2(h01, h23);
            *(uint2*)&Al[r * AP + c] = make_uint2(l01, l23);
        }
#pragma unroll
        for (int it = 0; it < 2; it++) {
            int f4 = tid + it * 256;
            int kk = f4 >> 5, c = (f4 & 31) << 2;
            float4 v = *(const float4*)(W + (size_t)(k0 + kk) * EE + col0 + c);
            uint32_t h01, h23, l01, l23;
            split2(v.x, v.y, h01, l01); split2(v.z, v.w, h23, l23);
            *(uint2*)&Bh[kk * BP + c] = make_uint2(h01, h23);
            *(uint2*)&Bl[kk * BP + c] = make_uint2(l01, l23);
        }
        __syncthreads();

        uint32_t a_h[4][4], a_l[4][4], b_h[4][2], b_l[4][2];
#pragma unroll
        for (int mi = 0; mi < 4; mi++) {
            int row = wm + mi * 16 + (lane & 15);
            int ko = (lane >> 4) << 3;
            ldsm4(a_h[mi][0], a_h[mi][1], a_h[mi][2], a_h[mi][3], &Ah[row * AP + ko]);
            ldsm4(a_l[mi][0], a_l[mi][1], a_l[mi][2], a_l[mi][3], &Al[row * AP + ko]);
        }
#pragma unroll
        for (int ni = 0; ni < 4; ni++) {
            int kr = (lane & 7) + (lane & 8);
            int nc = wn + ni * 8;
            ldsm2t(b_h[ni][0], b_h[ni][1], &Bh[kr * BP + nc]);
            ldsm2t(b_l[ni][0], b_l[ni][1], &Bl[kr * BP + nc]);
        }
#pragma unroll
        for (int mi = 0; mi < 4; mi++)
#pragma unroll
            for (int ni = 0; ni < 4; ni++) {
                mma_bf16(C[mi][ni], a_h[mi], b_h[ni]);
                mma_bf16(C[mi][ni], a_h[mi], b_l[ni]);
                mma_bf16(C[mi][ni], a_l[mi], b_h[ni]);
            }
        __syncthreads();
    }

#pragma unroll
    for (int mi = 0; mi < 4; mi++) {
#pragma unroll
        for (int half = 0; half < 2; half++) {
            int r = row0 + wm + mi * 16 + g + half * 8;
#pragma unroll
            for (int ni = 0; ni < 4; ni++) {
#pragma unroll
                for (int c01 = 0; c01 < 2; c01++) {
                    int n = col0 + wn + ni * 8 + 2 * tg + c01;
                    out[(size_t)r * EE + n] = C[mi][ni][half * 2 + c01] + bias[n];
                }
            }
        }
    }
}

// =================================================================================
// Kernel 2: single-pass causal attention, bf16 m16n8k16 via scalar-LDS fragments.
// All tiles stored k-contiguous (pairs packed in 32-bit words):
//   Q [row128][d], K [key64][d], P [row128][key64], V TRANSPOSED [d64][key64].
// pitch 72 bf16 => word pitch 36 (≡4 mod 32): inner-loop banks = 4g+tg, conflict-free.
// Scores 3-term, PV 3-term. Unnormalized e -> attn_w + g_l; rescale in kernel 2b.
// =================================================================================
#define QP 72   // bf16 pitch
#define KP 72
#define VP 72
#define PP 72
// byte offsets
#define OQH 0
#define OQL (OQH + 128 * QP * 2)     // 18432
#define OKH (OQL + 128 * QP * 2)     // 36864
#define OKL (OKH + 64 * KP * 2)      // 46080
#define OVH (OKL + 64 * KP * 2)      // 55296
#define OVL (OVH + 64 * VP * 2)      // 64512
#define OPH (OVL + 64 * VP * 2)      // 73728
#define OPL (OPH + 128 * PP * 2)     // 92160
#define ATT_SMEM (OPL + 128 * PP * 2)   // 110592

__global__ __launch_bounds__(256, 2) void attn_kernel(float* __restrict__ attn_w)
{
    extern __shared__ char smraw[];
    __nv_bfloat16* Qh = (__nv_bfloat16*)(smraw + OQH);
    __nv_bfloat16* Ql = (__nv_bfloat16*)(smraw + OQL);
    __nv_bfloat16* Kh = (__nv_bfloat16*)(smraw + OKH);
    __nv_bfloat16* Kl = (__nv_bfloat16*)(smraw + OKL);
    __nv_bfloat16* Vh = (__nv_bfloat16*)(smraw + OVH);
    __nv_bfloat16* Vl = (__nv_bfloat16*)(smraw + OVL);
    __nv_bfloat16* Ph = (__nv_bfloat16*)(smraw + OPH);
    __nv_bfloat16* Pl = (__nv_bfloat16*)(smraw + OPL);

    const int qb = (int)gridDim.x - 1 - (int)blockIdx.x;   // heavy blocks first
    const int h = blockIdx.y, b = blockIdx.z;
    const int tid = threadIdx.x;
    const int warp = tid >> 5, lane = tid & 31;
    const int g = lane >> 2, tg = lane & 3;

    const float* Qg = g_q + ((size_t)(b * HH + h) * SS + qb * 128) * DD;
    const float* Kg = g_k + (size_t)(b * HH + h) * SS * DD;
    const float* Vg = g_v + (size_t)(b * HH + h) * SS * DD;

    // ---- stage Q (pre-scaled by 1/8), [row][d] packed pairs ----
#pragma unroll
    for (int it = 0; it < 8; it++) {
        int f4 = tid + it * 256;
        int r = f4 >> 4, c = (f4 & 15) << 2;
        float4 v = *(const float4*)(Qg + r * 64 + c);
        uint32_t h01, h23, l01, l23;
        split2(v.x * 0.125f, v.y * 0.125f, h01, l01);
        split2(v.z * 0.125f, v.w * 0.125f, h23, l23);
        *(uint2*)&Qh[r * QP + c] = make_uint2(h01, h23);
        *(uint2*)&Ql[r * QP + c] = make_uint2(l01, l23);
    }
    __syncthreads();

    // ---- Q A-frags, register resident (4 k16-steps) ----
    uint32_t qa_h[4][4], qa_l[4][4];
    {
        int row = warp * 16 + g;
#pragma unroll
        for (int ks = 0; ks < 4; ks++) {
            int d0 = ks * 16 + 2 * tg;
            qa_h[ks][0] = *(uint32_t*)&Qh[row * QP + d0];
            qa_h[ks][1] = *(uint32_t*)&Qh[(row + 8) * QP + d0];
            qa_h[ks][2] = *(uint32_t*)&Qh[row * QP + d0 + 8];
            qa_h[ks][3] = *(uint32_t*)&Qh[(row + 8) * QP + d0 + 8];
            qa_l[ks][0] = *(uint32_t*)&Ql[row * QP + d0];
            qa_l[ks][1] = *(uint32_t*)&Ql[(row + 8) * QP + d0];
            qa_l[ks][2] = *(uint32_t*)&Ql[row * QP + d0 + 8];
            qa_l[ks][3] = *(uint32_t*)&Ql[(row + 8) * QP + d0 + 8];
        }
    }

    float accO[8][4];
#pragma unroll
    for (int dt = 0; dt < 8; dt++)
#pragma unroll
        for (int t = 0; t < 4; t++) accO[dt][t] = 0.f;
    float l0 = 0.f, l1 = 0.f;

    const int rowL = warp * 16 + g;
    const int row0g = qb * 128 + rowL;
    const size_t wbase = (size_t)(b * HH + h) * SS * SS;
    const int nch = 2 * (qb + 1);

    for (int ch = 0; ch < nch; ch++) {
        __syncthreads();
        // ---- stage K [key][d] packed; V transposed [d][key] ----
#pragma unroll
        for (int it = 0; it < 4; it++) {
            int f4 = tid + it * 256;
            int key = f4 >> 4, c = (f4 & 15) << 2;
            float4 kv = *(const float4*)(Kg + (size_t)(ch * 64 + key) * 64 + c);
            uint32_t h01, h23, l01, l23;
            split2(kv.x, kv.y, h01, l01); split2(kv.z, kv.w, h23, l23);
            *(uint2*)&Kh[key * KP + c] = make_uint2(h01, h23);
            *(uint2*)&Kl[key * KP + c] = make_uint2(l01, l23);

            float4 vv = *(const float4*)(Vg + (size_t)(ch * 64 + key) * 64 + c);
            float vs[4] = {vv.x, vv.y, vv.z, vv.w};
#pragma unroll
            for (int j = 0; j < 4; j++) {
                __nv_bfloat16 hb = __float2bfloat16_rn(vs[j]);
                Vh[(c + j) * VP + key] = hb;
                Vl[(c + j) * VP + key] = __float2bfloat16_rn(vs[j] - __bfloat162float(hb));
            }
        }
        __syncthreads();

        const bool masked = (ch >= 2 * qb);

        // ---- scores: 2 groups x 4 n-tiles (independent acc quads) ----
#pragma unroll 1
        for (int grp = 0; grp < 2; grp++) {
            float acc[4][4];
#pragma unroll
            for (int q = 0; q < 4; q++)
#pragma unroll
                for (int t = 0; t < 4; t++) acc[q][t] = 0.f;

#pragma unroll
            for (int ks = 0; ks < 4; ks++) {
                int d0 = ks * 16 + 2 * tg;
#pragma unroll
                for (int q = 0; q < 4; q++) {
                    int key = (grp * 4 + q) * 8 + g;
                    uint32_t bh[2], bl[2];
                    bh[0] = *(uint32_t*)&Kh[key * KP + d0];
                    bh[1] = *(uint32_t*)&Kh[key * KP + d0 + 8];
                    bl[0] = *(uint32_t*)&Kl[key * KP + d0];
                    bl[1] = *(uint32_t*)&Kl[key * KP + d0 + 8];
                    mma_bf16(acc[q], qa_h[ks], bh);
                    mma_bf16(acc[q], qa_h[ks], bl);
                    mma_bf16(acc[q], qa_l[ks], bh);
                }
            }

#pragma unroll
            for (int q = 0; q < 4; q++) {
                int nt = grp * 4 + q;
                int colb = ch * 64 + nt * 8 + 2 * tg;
                float e0, e1, e2, e3;
                if (masked) {
                    e0 = (colb     <= row0g)     ? __expf(acc[q][0]) : 0.f;
                    e1 = (colb + 1 <= row0g)     ? __expf(acc[q][1]) : 0.f;
                    e2 = (colb     <= row0g + 8) ? __expf(acc[q][2]) : 0.f;
                    e3 = (colb + 1 <= row0g + 8) ? __expf(acc[q][3]) : 0.f;
                } else {
                    e0 = __expf(acc[q][0]); e1 = __expf(acc[q][1]);
                    e2 = __expf(acc[q][2]); e3 = __expf(acc[q][3]);
                }
                l0 += e0 + e1; l1 += e2 + e3;
                size_t base = wbase + (size_t)row0g * SS + colb;
                *(float2*)(attn_w + base) = make_float2(e0, e1);
                *(float2*)(attn_w + base + (size_t)8 * SS) = make_float2(e2, e3);
                int pc = nt * 8 + 2 * tg;
                uint32_t ph01, pl01, ph23, pl23;
                split2(e0, e1, ph01, pl01);
                split2(e2, e3, ph23, pl23);
                *(uint32_t*)&Ph[rowL * PP + pc]       = ph01;
                *(uint32_t*)&Pl[rowL * PP + pc]       = pl01;
                *(uint32_t*)&Ph[(rowL + 8) * PP + pc] = ph23;
                *(uint32_t*)&Pl[(rowL + 8) * PP + pc] = pl23;
            }
        }
        __syncwarp();   // P rows are per-warp private

        // ---- O += P @ V (4 k16-steps, 8 independent accumulators) ----
#pragma unroll 1
        for (int ks = 0; ks < 4; ks++) {
            int k0 = ks * 16 + 2 * tg;
            uint32_t pa_h[4], pa_l[4];
            pa_h[0] = *(uint32_t*)&Ph[rowL * PP + k0];
            pa_h[1] = *(uint32_t*)&Ph[(rowL + 8) * PP + k0];
            pa_h[2] = *(uint32_t*)&Ph[rowL * PP + k0 + 8];
            pa_h[3] = *(uint32_t*)&Ph[(rowL + 8) * PP + k0 + 8];
            pa_l[0] = *(uint32_t*)&Pl[rowL * PP + k0];
            pa_l[1] = *(uint32_t*)&Pl[(rowL + 8) * PP + k0];
            pa_l[2] = *(uint32_t*)&Pl[rowL * PP + k0 + 8];
            pa_l[3] = *(uint32_t*)&Pl[(rowL + 8) * PP + k0 + 8];
#pragma unroll
            for (int dt = 0; dt < 8; dt++) {
                int d = dt * 8 + g;
                uint32_t bh[2], bl[2];
                bh[0] = *(uint32_t*)&Vh[d * VP + k0];
                bh[1] = *(uint32_t*)&Vh[d * VP + k0 + 8];
                bl[0] = *(uint32_t*)&Vl[d * VP + k0];
                bl[1] = *(uint32_t*)&Vl[d * VP + k0 + 8];
                mma_bf16(accO[dt], pa_h, bh);
                mma_bf16(accO[dt], pa_h, bl);
                mma_bf16(accO[dt], pa_l, bh);
            }
        }
    }

    // ---- row sums across quad; publish to g_l; write normalized O ----
#pragma unroll
    for (int o = 1; o < 4; o <<= 1) {
        l0 += __shfl_xor_sync(0xffffffffu, l0, o);
        l1 += __shfl_xor_sync(0xffffffffu, l1, o);
    }
    if (tg == 0) {
        g_l[(size_t)(b * HH + h) * SS + row0g] = l0;
        g_l[(size_t)(b * HH + h) * SS + row0g + 8] = l1;
    }
    float inv0 = 1.f / l0, inv1 = 1.f / l1;

#pragma unroll
    for (int dt = 0; dt < 8; dt++) {
        int col = h * 64 + dt * 8 + 2 * tg;
        *(float2*)&g_ctx[(size_t)(b * SS + row0g) * EE + col] =
            make_float2(accO[dt][0] * inv0, accO[dt][1] * inv0);
        *(float2*)&g_ctx[(size_t)(b * SS + row0g + 8) * EE + col] =
            make_float2(accO[dt][2] * inv1, accO[dt][3] * inv1);
    }
}

// =================================================================================
// Kernel 2b: rescale + zero-fill (verbatim from R6 — known good)
// =================================================================================
__global__ __launch_bounds__(256) void rescale_kernel(float* __restrict__ attn_w)
{
    const int row = blockIdx.x;
    const int s = row & (SS - 1);
    const float inv = 1.f / g_l[row];
    const int lim = s + 1;
    float* p = attn_w + (size_t)row * SS;

#pragma unroll
    for (int it = 0; it < 2; it++) {
        int c = (threadIdx.x + it * 256) << 2;
        float4 t;
        if (c + 3 < lim) {
            t = *(float4*)(p + c);
            t.x *= inv; t.y *= inv; t.z *= inv; t.w *= inv;
        } else if (c < lim) {
            t = *(float4*)(p + c);
            t.x = (c     < lim) ? t.x * inv : 0.f;
            t.y = (c + 1 < lim) ? t.y * inv : 0.f;
            t.z = (c + 2 < lim) ? t.z * inv : 0.f;
            t.w = (c + 3 < lim) ? t.w * inv : 0.f;
        } else {
            t = make_float4(0.f, 0.f, 0.f, 0.f);
        }
        *(float4*)(p + c) = t;
    }
}

// =================================================================================
// launch
// =================================================================================
extern "C" void kernel_launch(void* const* d_in, const int* in_sizes, int n_in,
                              void* d_out, int out_size)
{
    const float* hs = (const float*)d_in[0];
    const float* aw = (const float*)d_in[1];
    const float* ab = (const float*)d_in[2];
    const float* pw = (const float*)d_in[3];
    const float* pb = (const float*)d_in[4];

    float* out      = (float*)d_out;
    float* attn_out = out;                       // [2,2048,1024]
    float* attn_w   = out + (size_t)MM * EE;     // [2,16,2048,2048]

    cudaFuncSetAttribute(attn_kernel, cudaFuncAttributeMaxDynamicSharedMemorySize,
                         ATT_SMEM);

    qkv_gemm_bf16<<<dim3(NQKV / 128, MM / 128), 256>>>(hs, aw, ab);
    attn_kernel<<<dim3(SS / 128, HH, BB), 256, ATT_SMEM>>>(attn_w);
    rescale_kernel<<<BB * HH * SS, 256>>>(attn_w);
    proj_gemm_bf16<<<dim3(EE / 128, MM / 128), 256>>>(pw, pb, attn_out);
}